// round 2
// baseline (speedup 1.0000x reference)
#include <cuda_runtime.h>

// SlinkyForcePredictor — fully fused per-edge kernel.
//
// Key structural facts exploited (derived from reference, see analysis):
//  - edge e connects node 2e (src) -> 2e+1 (dst); every node in exactly one edge
//  - src nodes remain pure l=0 (50 scalars); only TP paths (0,0,0),(0,1,1),(0,2,2) are live
//  - their Wigner tensors are delta_{jk}/sqrt(2l+1) exactly
//  - messages are separable: msg[u,k] = h0[u]*w[u,p]*sh[k]*const
//  - even-node outputs are exactly zero
// => whole 3-layer network computed per-edge in one kernel, state in SMEM.

#define MULC 50
#define NBC 10
#define HIDC 100
#define TE 16          // edges per block = warps per block
#define NTHREADS 512

struct SM {
  float X[TE][MULC][12];      // dest features, rows padded to 12 floats (48B, f4-aligned)
  float s[TE][MULC];          // source scalar features
  float a[3][TE][52];         // a_p[u] = h0[u]*w[u][p]
  float shv[TE][12];          // spherical harmonics (9 used)
  float emb[TE][NBC];         // radial embedding
  float hid[TE][104];         // radial MLP hidden (100 used)
  // per-layer weights
  float Wsc[3][MULC][MULC];   // [l][u][v]
  float Wl1[MULC][MULC];      // Wlin1 l=0 block [u][v]
  float Wl2[3][MULC][MULC];   // [l][u][v]
  float Wg[MULC][MULC];       // [u][v]
  float W1[NBC][HIDC];        // [b][h]
  float b1[104];
  float W2[HIDC][152];        // [h][u*3+p] (only paths p=0..2 needed)
};

__device__ __forceinline__ float geluf(float x) {
  float x3 = x * x * x;
  float t = tanhf(0.7978845608028654f * (x + 0.044715f * x3));
  return 0.5f * x * (1.0f + t);
}
__device__ __forceinline__ float sigmoidf(float x) { return 1.0f / (1.0f + expf(-x)); }
__device__ __forceinline__ float siluf(float x) { return x * sigmoidf(x); }

__global__ __launch_bounds__(NTHREADS, 1)
void slinky_kernel(const float* __restrict__ node_pos,
                   const float* __restrict__ bar_alpha,
                   const float* __restrict__ W_embed,
                   const float* __restrict__ Wsc_g,
                   const float* __restrict__ Wlin1_g,
                   const float* __restrict__ W1_g,
                   const float* __restrict__ b1_g,
                   const float* __restrict__ W2_g,
                   const float* __restrict__ Wlin2_g,
                   const float* __restrict__ Wgate_g,
                   const float* __restrict__ Wout_g,
                   float* __restrict__ out)
{
  extern __shared__ __align__(16) float smem_raw[];
  SM* sm = reinterpret_cast<SM*>(smem_raw);

  const int tid = threadIdx.x;
  const int w   = tid >> 5;        // local edge index (warp id)
  const int ln  = tid & 31;        // lane
  const int e   = blockIdx.x * TE + w;
  const bool has2 = (ln < (MULC - 32));  // lanes 0..17 own a second channel
  const int u1 = ln + 32;

  const float INVS50 = 0.1414213562373095f;   // 1/sqrt(50)
  const float CS = 0.9238795325112867f;       // cos(pi/8)
  const float CX = 0.3826834323650898f;       // sin(pi/8)
  const float CXK0 = CX * 0.05773502691896258f;  // cx / sqrt(300)
  const float CXK1 = CX * 0.02357022603955159f;  // cx / sqrt(1800)
  const float CXK2 = CX * 0.01825741858350554f;  // cx / sqrt(3000)

  // ---------------- preprocess: edge geometry + state init ----------------
  {
    const float* p6 = node_pos + (size_t)e * 6;
    float ex = p6[1] - p6[0];
    float ey = p6[3] - p6[2];
    float ez = p6[5] - p6[4];
    float r = sqrtf(ex * ex + ey * ey + ez * ez);
    float inv = 1.0f / fmaxf(r, 1e-12f);
    float vx = ex * inv, vy = ey * inv, vz = ez * inv;
    if (ln == 0) {
      const float s3 = 1.7320508075688772f;
      const float s5 = 2.23606797749979f;
      const float s15 = 3.872983346207417f;
      float* shp = sm->shv[w];
      shp[0] = 1.0f;
      shp[1] = s3 * vx;
      shp[2] = s3 * vy;
      shp[3] = s3 * vz;
      shp[4] = s15 * vx * vz;
      shp[5] = s15 * vx * vy;
      shp[6] = s5 * (vy * vy - 0.5f * (vx * vx + vz * vz));
      shp[7] = s15 * vy * vz;
      shp[8] = 0.5f * s15 * (vz * vz - vx * vx);
    }
    if (ln < NBC) {
      const float step = 4.0f / 11.0f;
      float c = (float)(ln + 1) * step;
      float diff = (r - c) / step;
      float up = diff + 1.0f, um = 1.0f - diff;
      float ua = (up > 0.0f) ? expf(-1.0f / up) : 0.0f;
      float ub = (um > 0.0f) ? expf(-1.0f / um) : 0.0f;
      // 1.14136 * e^2 * sqrt(10)
      sm->emb[w][ln] = (1.14136f * 7.3890560989306495f * 3.1622776601683795f) * ua * ub;
    }
    float ba_s = bar_alpha[2 * e];
    float ba_d = bar_alpha[2 * e + 1];
    sm->s[w][ln] = ba_s * W_embed[ln];
    {
      float* xr = sm->X[w][ln];
      xr[0] = ba_d * W_embed[ln];
      #pragma unroll
      for (int k = 1; k < 9; k++) xr[k] = 0.0f;
    }
    if (has2) {
      sm->s[w][u1] = ba_s * W_embed[u1];
      float* xr = sm->X[w][u1];
      xr[0] = ba_d * W_embed[u1];
      #pragma unroll
      for (int k = 1; k < 9; k++) xr[k] = 0.0f;
    }
  }

  // ---------------- layers ----------------
  for (int i = 0; i < 3; i++) {
    __syncthreads();   // previous layer done; safe to overwrite weights
    // cooperative weight staging
    {
      const float* g = Wsc_g + i * 7500;
      float* d = &sm->Wsc[0][0][0];
      for (int t = tid; t < 7500; t += NTHREADS) d[t] = g[t];
      g = Wlin1_g + i * 7500;              // l=0 block is first 2500
      d = &sm->Wl1[0][0];
      for (int t = tid; t < 2500; t += NTHREADS) d[t] = g[t];
      g = Wlin2_g + i * 7500;
      d = &sm->Wl2[0][0][0];
      for (int t = tid; t < 7500; t += NTHREADS) d[t] = g[t];
      g = Wgate_g + i * 2500;
      d = &sm->Wg[0][0];
      for (int t = tid; t < 2500; t += NTHREADS) d[t] = g[t];
      g = W1_g + i * 1000;
      d = &sm->W1[0][0];
      for (int t = tid; t < 1000; t += NTHREADS) d[t] = g[t];
      if (tid < 100) sm->b1[tid] = b1_g[i * 100 + tid];
      g = W2_g + i * 75000;                // (100, 750); need cols u*15+p, p<3
      for (int t = tid; t < 15000; t += NTHREADS) {
        int h = t / 150;
        int c = t - h * 150;               // c = u*3 + p
        int u = c / 3;
        int p = c - u * 3;
        sm->W2[h][c] = g[h * 750 + u * 15 + p];
      }
    }
    __syncthreads();

    // ---- stage 1: radial MLP -> per-path weights w[u][p], p=0..2 ----
    #pragma unroll
    for (int j = 0; j < 4; j++) {
      int h = ln + 32 * j;
      if (h < HIDC) {
        float acc = 0.0f;
        #pragma unroll
        for (int b = 0; b < NBC; b++) acc = fmaf(sm->emb[w][b], sm->W1[b][h], acc);
        sm->hid[w][h] = geluf(acc * 0.31622776601683794f + sm->b1[h]);  // /sqrt(10)
      }
    }
    __syncwarp();
    float wv0[3] = {0.f, 0.f, 0.f};
    float wv1[3] = {0.f, 0.f, 0.f};
    {
      #pragma unroll 4
      for (int h = 0; h < HIDC; h++) {
        float hv = sm->hid[w][h];
        const float* r0 = &sm->W2[h][ln * 3];
        wv0[0] = fmaf(hv, r0[0], wv0[0]);
        wv0[1] = fmaf(hv, r0[1], wv0[1]);
        wv0[2] = fmaf(hv, r0[2], wv0[2]);
        if (has2) {
          const float* r1 = &sm->W2[h][u1 * 3];
          wv1[0] = fmaf(hv, r1[0], wv1[0]);
          wv1[1] = fmaf(hv, r1[1], wv1[1]);
          wv1[2] = fmaf(hv, r1[2], wv1[2]);
        }
      }
    }

    // ---- stage 2: source matvecs (h0 = lmix0(s,Wlin1), sc = lmix0(s,Wsc)) ----
    float h0a0 = 0.f, h0a1 = 0.f, sca0 = 0.f, sca1 = 0.f;
    {
      #pragma unroll 10
      for (int t = 0; t < MULC; t++) {
        float sv = sm->s[w][t];
        h0a0 = fmaf(sv, sm->Wl1[t][ln], h0a0);
        sca0 = fmaf(sv, sm->Wsc[0][t][ln], sca0);
        if (has2) {
          h0a1 = fmaf(sv, sm->Wl1[t][u1], h0a1);
          sca1 = fmaf(sv, sm->Wsc[0][t][u1], sca1);
        }
      }
    }
    __syncwarp();   // all lanes done reading s
    {
      float h0 = h0a0 * INVS50;
      sm->a[0][w][ln] = h0 * wv0[0] * 0.1f;
      sm->a[1][w][ln] = h0 * wv0[1] * 0.1f;
      sm->a[2][w][ln] = h0 * wv0[2] * 0.1f;
      sm->s[w][ln] = siluf(CS * sca0 * INVS50);
      if (has2) {
        float h1 = h0a1 * INVS50;
        sm->a[0][w][u1] = h1 * wv1[0] * 0.1f;
        sm->a[1][w][u1] = h1 * wv1[1] * 0.1f;
        sm->a[2][w][u1] = h1 * wv1[2] * 0.1f;
        sm->s[w][u1] = siluf(CS * sca1 * INVS50);
      }
    }
    __syncwarp();

    // ---- stage 3: dest update: cs*lmix(X,Wsc) + cx*lmix(agg,Wlin2) ----
    float acc0[9] = {0.f, 0.f, 0.f, 0.f, 0.f, 0.f, 0.f, 0.f, 0.f};
    float acc1[9] = {0.f, 0.f, 0.f, 0.f, 0.f, 0.f, 0.f, 0.f, 0.f};
    float bb0[3] = {0.f, 0.f, 0.f};
    float bb1[3] = {0.f, 0.f, 0.f};
    {
      #pragma unroll 5
      for (int u = 0; u < MULC; u++) {
        const float* xr = sm->X[w][u];
        float4 xA = *reinterpret_cast<const float4*>(xr);
        float4 xB = *reinterpret_cast<const float4*>(xr + 4);
        float x8 = xr[8];
        float a0 = sm->a[0][w][u];
        float a1 = sm->a[1][w][u];
        float a2 = sm->a[2][w][u];
        {
          float ws0 = sm->Wsc[0][u][ln];
          float ws1 = sm->Wsc[1][u][ln];
          float ws2 = sm->Wsc[2][u][ln];
          float l0 = sm->Wl2[0][u][ln];
          float l1 = sm->Wl2[1][u][ln];
          float l2 = sm->Wl2[2][u][ln];
          acc0[0] = fmaf(xA.x, ws0, acc0[0]);
          acc0[1] = fmaf(xA.y, ws1, acc0[1]);
          acc0[2] = fmaf(xA.z, ws1, acc0[2]);
          acc0[3] = fmaf(xA.w, ws1, acc0[3]);
          acc0[4] = fmaf(xB.x, ws2, acc0[4]);
          acc0[5] = fmaf(xB.y, ws2, acc0[5]);
          acc0[6] = fmaf(xB.z, ws2, acc0[6]);
          acc0[7] = fmaf(xB.w, ws2, acc0[7]);
          acc0[8] = fmaf(x8,   ws2, acc0[8]);
          bb0[0] = fmaf(a0, l0, bb0[0]);
          bb0[1] = fmaf(a1, l1, bb0[1]);
          bb0[2] = fmaf(a2, l2, bb0[2]);
        }
        if (has2) {
          float ws0 = sm->Wsc[0][u][u1];
          float ws1 = sm->Wsc[1][u][u1];
          float ws2 = sm->Wsc[2][u][u1];
          float l0 = sm->Wl2[0][u][u1];
          float l1 = sm->Wl2[1][u][u1];
          float l2 = sm->Wl2[2][u][u1];
          acc1[0] = fmaf(xA.x, ws0, acc1[0]);
          acc1[1] = fmaf(xA.y, ws1, acc1[1]);
          acc1[2] = fmaf(xA.z, ws1, acc1[2]);
          acc1[3] = fmaf(xA.w, ws1, acc1[3]);
          acc1[4] = fmaf(xB.x, ws2, acc1[4]);
          acc1[5] = fmaf(xB.y, ws2, acc1[5]);
          acc1[6] = fmaf(xB.z, ws2, acc1[6]);
          acc1[7] = fmaf(xB.w, ws2, acc1[7]);
          acc1[8] = fmaf(x8,   ws2, acc1[8]);
          bb1[0] = fmaf(a0, l0, bb1[0]);
          bb1[1] = fmaf(a1, l1, bb1[1]);
          bb1[2] = fmaf(a2, l2, bb1[2]);
        }
      }
    }
    float shl[9];
    #pragma unroll
    for (int k = 0; k < 9; k++) shl[k] = sm->shv[w][k];
    __syncwarp();   // all lanes done reading X
    {
      float* xr = sm->X[w][ln];
      xr[0] = CS * INVS50 * acc0[0] + CXK0 * bb0[0];
      #pragma unroll
      for (int k = 1; k < 4; k++) xr[k] = CS * INVS50 * acc0[k] + CXK1 * bb0[1] * shl[k];
      #pragma unroll
      for (int k = 4; k < 9; k++) xr[k] = CS * INVS50 * acc0[k] + CXK2 * bb0[2] * shl[k];
      if (has2) {
        float* xq = sm->X[w][u1];
        xq[0] = CS * INVS50 * acc1[0] + CXK0 * bb1[0];
        #pragma unroll
        for (int k = 1; k < 4; k++) xq[k] = CS * INVS50 * acc1[k] + CXK1 * bb1[1] * shl[k];
        #pragma unroll
        for (int k = 4; k < 9; k++) xq[k] = CS * INVS50 * acc1[k] + CXK2 * bb1[2] * shl[k];
      }
    }
    __syncwarp();

    // ---- stage 4: gate ----
    float ga0 = 0.f, ga1 = 0.f;
    {
      #pragma unroll 10
      for (int u = 0; u < MULC; u++) {
        float s0 = sm->X[w][u][0];
        ga0 = fmaf(s0, sm->Wg[u][ln], ga0);
        if (has2) ga1 = fmaf(s0, sm->Wg[u][u1], ga1);
      }
    }
    __syncwarp();   // all lanes done reading X[.][0]
    {
      float g0 = sigmoidf(ga0 * INVS50);
      float* xr = sm->X[w][ln];
      xr[0] = siluf(xr[0]);
      #pragma unroll
      for (int k = 1; k < 9; k++) xr[k] *= g0;
      if (has2) {
        float g1 = sigmoidf(ga1 * INVS50);
        float* xq = sm->X[w][u1];
        xq[0] = siluf(xq[0]);
        #pragma unroll
        for (int k = 1; k < 9; k++) xq[k] *= g1;
      }
    }
    __syncwarp();
  }

  // ---------------- output: only l=1 slice of dst nodes; src rows are zero ----------------
  {
    float wo0 = Wout_g[ln];
    const float* xr = sm->X[w][ln];
    float p0 = xr[1] * wo0;
    float p1 = xr[2] * wo0;
    float p2 = xr[3] * wo0;
    if (has2) {
      float wo1 = Wout_g[u1];
      const float* xq = sm->X[w][u1];
      p0 = fmaf(xq[1], wo1, p0);
      p1 = fmaf(xq[2], wo1, p1);
      p2 = fmaf(xq[3], wo1, p2);
    }
    #pragma unroll
    for (int off = 16; off; off >>= 1) {
      p0 += __shfl_xor_sync(0xffffffffu, p0, off);
      p1 += __shfl_xor_sync(0xffffffffu, p1, off);
      p2 += __shfl_xor_sync(0xffffffffu, p2, off);
    }
    if (ln == 0) {
      float* od = out + (size_t)(2 * e) * 3;
      od[0] = 0.0f; od[1] = 0.0f; od[2] = 0.0f;    // even (src) node: exactly zero
      od[3] = p0 * INVS50;
      od[4] = p1 * INVS50;
      od[5] = p2 * INVS50;
    }
  }
}

extern "C" void kernel_launch(void* const* d_in, const int* in_sizes, int n_in,
                              void* d_out, int out_size) {
  const float* node_pos = (const float*)d_in[0];
  const float* bar_alpha = (const float*)d_in[1];
  const float* W_embed  = (const float*)d_in[2];
  const float* Wsc      = (const float*)d_in[3];
  const float* Wlin1    = (const float*)d_in[4];
  const float* W1       = (const float*)d_in[5];
  const float* b1       = (const float*)d_in[6];
  const float* W2       = (const float*)d_in[7];
  const float* Wlin2    = (const float*)d_in[8];
  const float* Wgate    = (const float*)d_in[9];
  const float* W_out    = (const float*)d_in[10];
  float* out = (float*)d_out;

  int E = in_sizes[0] / 6;          // 40000 (divisible by TE=16)
  size_t smem = sizeof(SM);
  cudaFuncSetAttribute(slinky_kernel, cudaFuncAttributeMaxDynamicSharedMemorySize, (int)smem);
  slinky_kernel<<<E / TE, NTHREADS, smem>>>(node_pos, bar_alpha, W_embed, Wsc, Wlin1,
                                            W1, b1, W2, Wlin2, Wgate, W_out, out);
}

// round 3
// speedup vs baseline: 1.2599x; 1.2599x over previous
#include <cuda_runtime.h>

// SlinkyForcePredictor — fused per-edge kernel, v2.
// R1 established the structural collapse (src nodes pure l=0; 3 live TP paths;
// delta Wigner tensors; separable messages; even-node outputs zero).
// R2: LDS-bound per ncu (L1 78%, fma 21%) -> raise FMA:LDS ratio:
//   - 2 edges per warp (weight LDS amortized over 2 edges)
//   - channel-pair lanes: lane ln owns channels (2ln, 2ln+1), float2 weight loads
//   - a[p][u] folded into X row padding slots 9..11 (stage3 row = 3x LDS.128)

#define MULC 50
#define NBC 10
#define HIDC 100
#define TE 20          // edges per block
#define NW 10          // warps per block (2 edges each)
#define NTHREADS 320

struct SM {
  float X[TE][MULC][12];      // dest features; slots 0..8 = x, 9..11 = a0..a2
  float s[TE][MULC];          // source scalar features
  float shv[TE][12];          // spherical harmonics (9 used)
  float emb[TE][12];          // radial embedding (10 used)
  float hid[TE][104];         // radial MLP hidden (100 used)
  // per-layer weights
  float Wsc[3][MULC][MULC];   // [l][u][v]
  float Wl1[MULC][MULC];      // Wlin1 l=0 block [u][v]
  float Wl2[3][MULC][MULC];   // [l][u][v]
  float Wg[MULC][MULC];       // [u][v]
  float W1[NBC][HIDC];        // [b][h]
  float b1[104];
  float W2[HIDC][152];        // [h][u*3+p], p=0..2
};

__device__ __forceinline__ float geluf(float x) {
  float x3 = x * x * x;
  float t = tanhf(0.7978845608028654f * (x + 0.044715f * x3));
  return 0.5f * x * (1.0f + t);
}
__device__ __forceinline__ float sigmoidf(float x) { return 1.0f / (1.0f + expf(-x)); }
__device__ __forceinline__ float siluf(float x) { return x * sigmoidf(x); }

__global__ __launch_bounds__(NTHREADS, 1)
void slinky_kernel(const float* __restrict__ node_pos,
                   const float* __restrict__ bar_alpha,
                   const float* __restrict__ W_embed,
                   const float* __restrict__ Wsc_g,
                   const float* __restrict__ Wlin1_g,
                   const float* __restrict__ W1_g,
                   const float* __restrict__ b1_g,
                   const float* __restrict__ W2_g,
                   const float* __restrict__ Wlin2_g,
                   const float* __restrict__ Wgate_g,
                   const float* __restrict__ Wout_g,
                   float* __restrict__ out)
{
  extern __shared__ __align__(16) float smem_raw[];
  SM* sm = reinterpret_cast<SM*>(smem_raw);

  const int tid = threadIdx.x;
  const int w   = tid >> 5;        // warp id, owns local edges 2w, 2w+1
  const int ln  = tid & 31;
  const int e0  = 2 * w;           // local edge indices
  const int e1  = 2 * w + 1;
  const bool act = (ln < 25);      // lanes 0..24 own channel pair (2ln, 2ln+1)
  const int u0 = 2 * ln;

  const float INVS50 = 0.1414213562373095f;   // 1/sqrt(50)
  const float CS = 0.9238795325112867f;       // cos(pi/8)
  const float CX = 0.3826834323650898f;       // sin(pi/8)
  const float CXK0 = CX * 0.05773502691896258f;  // cx / sqrt(300)
  const float CXK1 = CX * 0.02357022603955159f;  // cx / sqrt(1800)
  const float CXK2 = CX * 0.01825741858350554f;  // cx / sqrt(3000)

  // ---------------- preprocess ----------------
  {
    // half-warp per edge for geometry
    const int half = ln >> 4;
    const int l16 = ln & 15;
    const int le = e0 + half;
    const int eg = blockIdx.x * TE + le;
    const float* p6 = node_pos + (size_t)eg * 6;
    float ex = p6[1] - p6[0];
    float ey = p6[3] - p6[2];
    float ez = p6[5] - p6[4];
    float r = sqrtf(ex * ex + ey * ey + ez * ez);
    float inv = 1.0f / fmaxf(r, 1e-12f);
    float vx = ex * inv, vy = ey * inv, vz = ez * inv;
    if (l16 == 0) {
      const float s3 = 1.7320508075688772f;
      const float s5 = 2.23606797749979f;
      const float s15 = 3.872983346207417f;
      float* shp = sm->shv[le];
      shp[0] = 1.0f;
      shp[1] = s3 * vx;
      shp[2] = s3 * vy;
      shp[3] = s3 * vz;
      shp[4] = s15 * vx * vz;
      shp[5] = s15 * vx * vy;
      shp[6] = s5 * (vy * vy - 0.5f * (vx * vx + vz * vz));
      shp[7] = s15 * vy * vz;
      shp[8] = 0.5f * s15 * (vz * vz - vx * vx);
    }
    if (l16 < NBC) {
      const float step = 4.0f / 11.0f;
      float c = (float)(l16 + 1) * step;
      float diff = (r - c) / step;
      float up = diff + 1.0f, um = 1.0f - diff;
      float ua = (up > 0.0f) ? expf(-1.0f / up) : 0.0f;
      float ub = (um > 0.0f) ? expf(-1.0f / um) : 0.0f;
      sm->emb[le][l16] = (1.14136f * 7.3890560989306495f * 3.1622776601683795f) * ua * ub;
    }
  }
  if (act) {
    const int geb = blockIdx.x * TE;
    #pragma unroll
    for (int e = 0; e < 2; e++) {
      int le = e0 + e;
      int eg = geb + le;
      float ba_s = bar_alpha[2 * eg];
      float ba_d = bar_alpha[2 * eg + 1];
      #pragma unroll
      for (int ch = 0; ch < 2; ch++) {
        int u = u0 + ch;
        float we = W_embed[u];
        sm->s[le][u] = ba_s * we;
        float* xr = sm->X[le][u];
        xr[0] = ba_d * we;
        #pragma unroll
        for (int k = 1; k < 9; k++) xr[k] = 0.0f;
      }
    }
  }

  float v[2][2][9];   // post-layer features for own channels (live across stages)

  // ---------------- layers ----------------
  for (int i = 0; i < 3; i++) {
    __syncthreads();
    // cooperative weight staging
    {
      const float* g = Wsc_g + i * 7500;
      float* d = &sm->Wsc[0][0][0];
      for (int t = tid; t < 7500; t += NTHREADS) d[t] = g[t];
      g = Wlin1_g + i * 7500;               // l=0 block first 2500
      d = &sm->Wl1[0][0];
      for (int t = tid; t < 2500; t += NTHREADS) d[t] = g[t];
      g = Wlin2_g + i * 7500;
      d = &sm->Wl2[0][0][0];
      for (int t = tid; t < 7500; t += NTHREADS) d[t] = g[t];
      g = Wgate_g + i * 2500;
      d = &sm->Wg[0][0];
      for (int t = tid; t < 2500; t += NTHREADS) d[t] = g[t];
      g = W1_g + i * 1000;
      d = &sm->W1[0][0];
      for (int t = tid; t < 1000; t += NTHREADS) d[t] = g[t];
      if (tid < 100) sm->b1[tid] = b1_g[i * 100 + tid];
      g = W2_g + i * 75000;                 // (100,750); need cols u*15+p, p<3
      for (int t = tid; t < 15000; t += NTHREADS) {
        int h = t / 150;
        int c = t - h * 150;                // c = u*3 + p
        int u = c / 3;
        int p = c - u * 3;
        sm->W2[h][c] = g[h * 750 + u * 15 + p];
      }
    }
    __syncthreads();

    // ---- stage 1a: radial MLP hidden (lanes cover h) ----
    #pragma unroll
    for (int j = 0; j < 4; j++) {
      int h = ln + 32 * j;
      if (h < HIDC) {
        float a0 = 0.0f, a1 = 0.0f;
        #pragma unroll
        for (int b = 0; b < NBC; b++) {
          float w1 = sm->W1[b][h];
          a0 = fmaf(sm->emb[e0][b], w1, a0);
          a1 = fmaf(sm->emb[e1][b], w1, a1);
        }
        sm->hid[e0][h] = geluf(a0 * 0.31622776601683794f + sm->b1[h]);
        sm->hid[e1][h] = geluf(a1 * 0.31622776601683794f + sm->b1[h]);
      }
    }
    __syncwarp();

    // ---- stage 1b: wv[edge][ch][p] = sum_h hid*W2 ----
    float wv[2][2][3] = {};
    if (act) {
      #pragma unroll 4
      for (int h = 0; h < HIDC; h++) {
        float h0v = sm->hid[e0][h];
        float h1v = sm->hid[e1][h];
        const float2* w2p = reinterpret_cast<const float2*>(&sm->W2[h][6 * ln]);
        float2 c0 = w2p[0], c1 = w2p[1], c2 = w2p[2];
        wv[0][0][0] = fmaf(h0v, c0.x, wv[0][0][0]);
        wv[0][0][1] = fmaf(h0v, c0.y, wv[0][0][1]);
        wv[0][0][2] = fmaf(h0v, c1.x, wv[0][0][2]);
        wv[0][1][0] = fmaf(h0v, c1.y, wv[0][1][0]);
        wv[0][1][1] = fmaf(h0v, c2.x, wv[0][1][1]);
        wv[0][1][2] = fmaf(h0v, c2.y, wv[0][1][2]);
        wv[1][0][0] = fmaf(h1v, c0.x, wv[1][0][0]);
        wv[1][0][1] = fmaf(h1v, c0.y, wv[1][0][1]);
        wv[1][0][2] = fmaf(h1v, c1.x, wv[1][0][2]);
        wv[1][1][0] = fmaf(h1v, c1.y, wv[1][1][0]);
        wv[1][1][1] = fmaf(h1v, c2.x, wv[1][1][1]);
        wv[1][1][2] = fmaf(h1v, c2.y, wv[1][1][2]);
      }
    }

    // ---- stage 2: source matvecs h0 = s@Wlin1, sc = s@Wsc0 ----
    float h0a[2][2] = {};
    float sca[2][2] = {};
    if (act) {
      #pragma unroll 5
      for (int t = 0; t < MULC; t++) {
        float s0 = sm->s[e0][t];
        float s1 = sm->s[e1][t];
        float2 wl = *reinterpret_cast<const float2*>(&sm->Wl1[t][u0]);
        float2 ws = *reinterpret_cast<const float2*>(&sm->Wsc[0][t][u0]);
        h0a[0][0] = fmaf(s0, wl.x, h0a[0][0]);
        h0a[0][1] = fmaf(s0, wl.y, h0a[0][1]);
        sca[0][0] = fmaf(s0, ws.x, sca[0][0]);
        sca[0][1] = fmaf(s0, ws.y, sca[0][1]);
        h0a[1][0] = fmaf(s1, wl.x, h0a[1][0]);
        h0a[1][1] = fmaf(s1, wl.y, h0a[1][1]);
        sca[1][0] = fmaf(s1, ws.x, sca[1][0]);
        sca[1][1] = fmaf(s1, ws.y, sca[1][1]);
      }
    }
    __syncwarp();   // all lanes done reading s
    if (act) {
      #pragma unroll
      for (int e = 0; e < 2; e++) {
        int le = e0 + e;
        #pragma unroll
        for (int ch = 0; ch < 2; ch++) {
          int u = u0 + ch;
          float h0 = h0a[e][ch] * INVS50;
          float* xr = sm->X[le][u];
          xr[9]  = h0 * wv[e][ch][0] * 0.1f;
          xr[10] = h0 * wv[e][ch][1] * 0.1f;
          xr[11] = h0 * wv[e][ch][2] * 0.1f;
          sm->s[le][u] = siluf(CS * sca[e][ch] * INVS50);
        }
      }
    }
    __syncwarp();

    // ---- stage 3: dest update: cs*lmix(X,Wsc) + cx*lmix(agg,Wlin2) ----
    float acc[2][2][9] = {};
    float bb[2][2][3] = {};
    if (act) {
      #pragma unroll 5
      for (int u = 0; u < MULC; u++) {
        const float4* x0p = reinterpret_cast<const float4*>(sm->X[e0][u]);
        float4 A0 = x0p[0], B0 = x0p[1], C0 = x0p[2];
        const float4* x1p = reinterpret_cast<const float4*>(sm->X[e1][u]);
        float4 A1 = x1p[0], B1 = x1p[1], C1 = x1p[2];
        float2 ws0 = *reinterpret_cast<const float2*>(&sm->Wsc[0][u][u0]);
        float2 ws1 = *reinterpret_cast<const float2*>(&sm->Wsc[1][u][u0]);
        float2 ws2 = *reinterpret_cast<const float2*>(&sm->Wsc[2][u][u0]);
        float2 l0 = *reinterpret_cast<const float2*>(&sm->Wl2[0][u][u0]);
        float2 l1 = *reinterpret_cast<const float2*>(&sm->Wl2[1][u][u0]);
        float2 l2 = *reinterpret_cast<const float2*>(&sm->Wl2[2][u][u0]);
        // edge 0
        acc[0][0][0] = fmaf(A0.x, ws0.x, acc[0][0][0]);
        acc[0][0][1] = fmaf(A0.y, ws1.x, acc[0][0][1]);
        acc[0][0][2] = fmaf(A0.z, ws1.x, acc[0][0][2]);
        acc[0][0][3] = fmaf(A0.w, ws1.x, acc[0][0][3]);
        acc[0][0][4] = fmaf(B0.x, ws2.x, acc[0][0][4]);
        acc[0][0][5] = fmaf(B0.y, ws2.x, acc[0][0][5]);
        acc[0][0][6] = fmaf(B0.z, ws2.x, acc[0][0][6]);
        acc[0][0][7] = fmaf(B0.w, ws2.x, acc[0][0][7]);
        acc[0][0][8] = fmaf(C0.x, ws2.x, acc[0][0][8]);
        bb[0][0][0]  = fmaf(C0.y, l0.x, bb[0][0][0]);
        bb[0][0][1]  = fmaf(C0.z, l1.x, bb[0][0][1]);
        bb[0][0][2]  = fmaf(C0.w, l2.x, bb[0][0][2]);
        acc[0][1][0] = fmaf(A0.x, ws0.y, acc[0][1][0]);
        acc[0][1][1] = fmaf(A0.y, ws1.y, acc[0][1][1]);
        acc[0][1][2] = fmaf(A0.z, ws1.y, acc[0][1][2]);
        acc[0][1][3] = fmaf(A0.w, ws1.y, acc[0][1][3]);
        acc[0][1][4] = fmaf(B0.x, ws2.y, acc[0][1][4]);
        acc[0][1][5] = fmaf(B0.y, ws2.y, acc[0][1][5]);
        acc[0][1][6] = fmaf(B0.z, ws2.y, acc[0][1][6]);
        acc[0][1][7] = fmaf(B0.w, ws2.y, acc[0][1][7]);
        acc[0][1][8] = fmaf(C0.x, ws2.y, acc[0][1][8]);
        bb[0][1][0]  = fmaf(C0.y, l0.y, bb[0][1][0]);
        bb[0][1][1]  = fmaf(C0.z, l1.y, bb[0][1][1]);
        bb[0][1][2]  = fmaf(C0.w, l2.y, bb[0][1][2]);
        // edge 1
        acc[1][0][0] = fmaf(A1.x, ws0.x, acc[1][0][0]);
        acc[1][0][1] = fmaf(A1.y, ws1.x, acc[1][0][1]);
        acc[1][0][2] = fmaf(A1.z, ws1.x, acc[1][0][2]);
        acc[1][0][3] = fmaf(A1.w, ws1.x, acc[1][0][3]);
        acc[1][0][4] = fmaf(B1.x, ws2.x, acc[1][0][4]);
        acc[1][0][5] = fmaf(B1.y, ws2.x, acc[1][0][5]);
        acc[1][0][6] = fmaf(B1.z, ws2.x, acc[1][0][6]);
        acc[1][0][7] = fmaf(B1.w, ws2.x, acc[1][0][7]);
        acc[1][0][8] = fmaf(C1.x, ws2.x, acc[1][0][8]);
        bb[1][0][0]  = fmaf(C1.y, l0.x, bb[1][0][0]);
        bb[1][0][1]  = fmaf(C1.z, l1.x, bb[1][0][1]);
        bb[1][0][2]  = fmaf(C1.w, l2.x, bb[1][0][2]);
        acc[1][1][0] = fmaf(A1.x, ws0.y, acc[1][1][0]);
        acc[1][1][1] = fmaf(A1.y, ws1.y, acc[1][1][1]);
        acc[1][1][2] = fmaf(A1.z, ws1.y, acc[1][1][2]);
        acc[1][1][3] = fmaf(A1.w, ws1.y, acc[1][1][3]);
        acc[1][1][4] = fmaf(B1.x, ws2.y, acc[1][1][4]);
        acc[1][1][5] = fmaf(B1.y, ws2.y, acc[1][1][5]);
        acc[1][1][6] = fmaf(B1.z, ws2.y, acc[1][1][6]);
        acc[1][1][7] = fmaf(B1.w, ws2.y, acc[1][1][7]);
        acc[1][1][8] = fmaf(C1.x, ws2.y, acc[1][1][8]);
        bb[1][1][0]  = fmaf(C1.y, l0.y, bb[1][1][0]);
        bb[1][1][1]  = fmaf(C1.z, l1.y, bb[1][1][1]);
        bb[1][1][2]  = fmaf(C1.w, l2.y, bb[1][1][2]);
      }
    }
    __syncwarp();   // all lanes done reading X
    if (act) {
      #pragma unroll
      for (int e = 0; e < 2; e++) {
        int le = e0 + e;
        const float* shl = sm->shv[le];
        #pragma unroll
        for (int ch = 0; ch < 2; ch++) {
          int u = u0 + ch;
          v[e][ch][0] = CS * INVS50 * acc[e][ch][0] + CXK0 * bb[e][ch][0];
          #pragma unroll
          for (int k = 1; k < 4; k++)
            v[e][ch][k] = CS * INVS50 * acc[e][ch][k] + CXK1 * bb[e][ch][1] * shl[k];
          #pragma unroll
          for (int k = 4; k < 9; k++)
            v[e][ch][k] = CS * INVS50 * acc[e][ch][k] + CXK2 * bb[e][ch][2] * shl[k];
          sm->X[le][u][0] = v[e][ch][0];   // only slot 0 needed for gate matvec
        }
      }
    }
    __syncwarp();

    // ---- stage 4: gate ----
    float ga[2][2] = {};
    if (act) {
      #pragma unroll 5
      for (int u = 0; u < MULC; u++) {
        float t0 = sm->X[e0][u][0];
        float t1 = sm->X[e1][u][0];
        float2 wg = *reinterpret_cast<const float2*>(&sm->Wg[u][u0]);
        ga[0][0] = fmaf(t0, wg.x, ga[0][0]);
        ga[0][1] = fmaf(t0, wg.y, ga[0][1]);
        ga[1][0] = fmaf(t1, wg.x, ga[1][0]);
        ga[1][1] = fmaf(t1, wg.y, ga[1][1]);
      }
    }
    __syncwarp();
    if (act) {
      #pragma unroll
      for (int e = 0; e < 2; e++) {
        int le = e0 + e;
        #pragma unroll
        for (int ch = 0; ch < 2; ch++) {
          int u = u0 + ch;
          float g = sigmoidf(ga[e][ch] * INVS50);
          v[e][ch][0] = siluf(v[e][ch][0]);
          #pragma unroll
          for (int k = 1; k < 9; k++) v[e][ch][k] *= g;
          // store gated row (slots 0..8) for next layer
          float* xr = sm->X[le][u];
          float4 q0 = make_float4(v[e][ch][0], v[e][ch][1], v[e][ch][2], v[e][ch][3]);
          float4 q1 = make_float4(v[e][ch][4], v[e][ch][5], v[e][ch][6], v[e][ch][7]);
          *reinterpret_cast<float4*>(xr)     = q0;
          *reinterpret_cast<float4*>(xr + 4) = q1;
          xr[8] = v[e][ch][8];
        }
      }
    }
    __syncwarp();
  }

  // ---------------- output: only l=1 slice of dst nodes ----------------
  {
    float p[2][3] = {};
    if (act) {
      #pragma unroll
      for (int e = 0; e < 2; e++) {
        float wo0 = Wout_g[u0];
        float wo1 = Wout_g[u0 + 1];
        p[e][0] = v[e][0][1] * wo0 + v[e][1][1] * wo1;
        p[e][1] = v[e][0][2] * wo0 + v[e][1][2] * wo1;
        p[e][2] = v[e][0][3] * wo0 + v[e][1][3] * wo1;
      }
    }
    #pragma unroll
    for (int off = 16; off; off >>= 1) {
      #pragma unroll
      for (int e = 0; e < 2; e++) {
        p[e][0] += __shfl_xor_sync(0xffffffffu, p[e][0], off);
        p[e][1] += __shfl_xor_sync(0xffffffffu, p[e][1], off);
        p[e][2] += __shfl_xor_sync(0xffffffffu, p[e][2], off);
      }
    }
    if (ln == 0) {
      int eg0 = blockIdx.x * TE + e0;
      float* od = out + (size_t)(2 * eg0) * 3;   // 4 consecutive node rows
      od[0] = 0.0f; od[1] = 0.0f; od[2] = 0.0f;            // src node of edge 0
      od[3] = p[0][0] * INVS50;
      od[4] = p[0][1] * INVS50;
      od[5] = p[0][2] * INVS50;
      od[6] = 0.0f; od[7] = 0.0f; od[8] = 0.0f;            // src node of edge 1
      od[9]  = p[1][0] * INVS50;
      od[10] = p[1][1] * INVS50;
      od[11] = p[1][2] * INVS50;
    }
  }
}

extern "C" void kernel_launch(void* const* d_in, const int* in_sizes, int n_in,
                              void* d_out, int out_size) {
  const float* node_pos = (const float*)d_in[0];
  const float* bar_alpha = (const float*)d_in[1];
  const float* W_embed  = (const float*)d_in[2];
  const float* Wsc      = (const float*)d_in[3];
  const float* Wlin1    = (const float*)d_in[4];
  const float* W1       = (const float*)d_in[5];
  const float* b1       = (const float*)d_in[6];
  const float* W2       = (const float*)d_in[7];
  const float* Wlin2    = (const float*)d_in[8];
  const float* Wgate    = (const float*)d_in[9];
  const float* W_out    = (const float*)d_in[10];
  float* out = (float*)d_out;

  int E = in_sizes[0] / 6;          // 40000, divisible by TE=20
  size_t smem = sizeof(SM);
  cudaFuncSetAttribute(slinky_kernel, cudaFuncAttributeMaxDynamicSharedMemorySize, (int)smem);
  slinky_kernel<<<E / TE, NTHREADS, smem>>>(node_pos, bar_alpha, W_embed, Wsc, Wlin1,
                                            W1, b1, W2, Wlin2, Wgate, W_out, out);
}

// round 4
// speedup vs baseline: 1.5643x; 1.2416x over previous
#include <cuda_runtime.h>

// SlinkyForcePredictor — fused per-edge kernel, v3.
// v2 was latency-bound (occ 15.3%, issue 43%, nothing saturated).
// v3: 512 threads / 16 warps / TE=32 edges per block (2 edges/warp kept).
//   - hid[] folded into X row padding slots 9/10 (saves 13.3KB -> SMEM fits)
//   - v[] register array removed (write X back after stage3; gate rereads)
//   - __launch_bounds__(512) -> 128-reg cap

#define MULC 50
#define NBC 10
#define HIDC 100
#define TE 32          // edges per block
#define NTHREADS 512   // 16 warps, 2 edges each

struct SM {
  float X[TE][MULC][12];      // slots 0..8 = x; 9..11 = hid overlay then a0..a2
  float s[TE][MULC];
  float shv[TE][12];
  float emb[TE][12];
  float Wsc[3][MULC][MULC];
  float Wl1[MULC][MULC];
  float Wl2[3][MULC][MULC];
  float Wg[MULC][MULC];
  float W1[NBC][HIDC];
  float b1[104];
  float W2[HIDC][152];        // [h][u*3+p]
};

#define HID(le,h) sm->X[le][(h) >> 1][9 + ((h) & 1)]

__device__ __forceinline__ float geluf(float x) {
  float x3 = x * x * x;
  float t = tanhf(0.7978845608028654f * (x + 0.044715f * x3));
  return 0.5f * x * (1.0f + t);
}
__device__ __forceinline__ float sigmoidf(float x) { return 1.0f / (1.0f + expf(-x)); }
__device__ __forceinline__ float siluf(float x) { return x * sigmoidf(x); }

__global__ __launch_bounds__(NTHREADS, 1)
void slinky_kernel(const float* __restrict__ node_pos,
                   const float* __restrict__ bar_alpha,
                   const float* __restrict__ W_embed,
                   const float* __restrict__ Wsc_g,
                   const float* __restrict__ Wlin1_g,
                   const float* __restrict__ W1_g,
                   const float* __restrict__ b1_g,
                   const float* __restrict__ W2_g,
                   const float* __restrict__ Wlin2_g,
                   const float* __restrict__ Wgate_g,
                   const float* __restrict__ Wout_g,
                   float* __restrict__ out)
{
  extern __shared__ __align__(16) float smem_raw[];
  SM* sm = reinterpret_cast<SM*>(smem_raw);

  const int tid = threadIdx.x;
  const int w   = tid >> 5;
  const int ln  = tid & 31;
  const int e0  = 2 * w;
  const int e1  = 2 * w + 1;
  const bool act = (ln < 25);
  const int u0 = 2 * ln;

  const float INVS50 = 0.1414213562373095f;
  const float CS = 0.9238795325112867f;
  const float CX = 0.3826834323650898f;
  const float CXK0 = CX * 0.05773502691896258f;
  const float CXK1 = CX * 0.02357022603955159f;
  const float CXK2 = CX * 0.01825741858350554f;

  // ---------------- preprocess ----------------
  {
    const int half = ln >> 4;
    const int l16 = ln & 15;
    const int le = e0 + half;
    const int eg = blockIdx.x * TE + le;
    const float* p6 = node_pos + (size_t)eg * 6;
    float ex = p6[1] - p6[0];
    float ey = p6[3] - p6[2];
    float ez = p6[5] - p6[4];
    float r = sqrtf(ex * ex + ey * ey + ez * ez);
    float inv = 1.0f / fmaxf(r, 1e-12f);
    float vx = ex * inv, vy = ey * inv, vz = ez * inv;
    if (l16 == 0) {
      const float s3 = 1.7320508075688772f;
      const float s5 = 2.23606797749979f;
      const float s15 = 3.872983346207417f;
      float* shp = sm->shv[le];
      shp[0] = 1.0f;
      shp[1] = s3 * vx;
      shp[2] = s3 * vy;
      shp[3] = s3 * vz;
      shp[4] = s15 * vx * vz;
      shp[5] = s15 * vx * vy;
      shp[6] = s5 * (vy * vy - 0.5f * (vx * vx + vz * vz));
      shp[7] = s15 * vy * vz;
      shp[8] = 0.5f * s15 * (vz * vz - vx * vx);
    }
    if (l16 < NBC) {
      const float step = 4.0f / 11.0f;
      float c = (float)(l16 + 1) * step;
      float diff = (r - c) / step;
      float up = diff + 1.0f, um = 1.0f - diff;
      float ua = (up > 0.0f) ? expf(-1.0f / up) : 0.0f;
      float ub = (um > 0.0f) ? expf(-1.0f / um) : 0.0f;
      sm->emb[le][l16] = (1.14136f * 7.3890560989306495f * 3.1622776601683795f) * ua * ub;
    }
  }
  if (act) {
    const int geb = blockIdx.x * TE;
    #pragma unroll
    for (int e = 0; e < 2; e++) {
      int le = e0 + e;
      int eg = geb + le;
      float ba_s = bar_alpha[2 * eg];
      float ba_d = bar_alpha[2 * eg + 1];
      #pragma unroll
      for (int ch = 0; ch < 2; ch++) {
        int u = u0 + ch;
        float we = W_embed[u];
        sm->s[le][u] = ba_s * we;
        float* xr = sm->X[le][u];
        xr[0] = ba_d * we;
        #pragma unroll
        for (int k = 1; k < 9; k++) xr[k] = 0.0f;
      }
    }
  }

  // ---------------- layers ----------------
  for (int i = 0; i < 3; i++) {
    __syncthreads();
    // cooperative weight staging (float4 where contiguous)
    {
      const float4* g4 = reinterpret_cast<const float4*>(Wsc_g + i * 7500);
      float4* d4 = reinterpret_cast<float4*>(&sm->Wsc[0][0][0]);
      for (int t = tid; t < 1875; t += NTHREADS) d4[t] = g4[t];
      g4 = reinterpret_cast<const float4*>(Wlin1_g + i * 7500);
      d4 = reinterpret_cast<float4*>(&sm->Wl1[0][0]);
      for (int t = tid; t < 625; t += NTHREADS) d4[t] = g4[t];
      g4 = reinterpret_cast<const float4*>(Wlin2_g + i * 7500);
      d4 = reinterpret_cast<float4*>(&sm->Wl2[0][0][0]);
      for (int t = tid; t < 1875; t += NTHREADS) d4[t] = g4[t];
      g4 = reinterpret_cast<const float4*>(Wgate_g + i * 2500);
      d4 = reinterpret_cast<float4*>(&sm->Wg[0][0]);
      for (int t = tid; t < 625; t += NTHREADS) d4[t] = g4[t];
      g4 = reinterpret_cast<const float4*>(W1_g + i * 1000);
      d4 = reinterpret_cast<float4*>(&sm->W1[0][0]);
      for (int t = tid; t < 250; t += NTHREADS) d4[t] = g4[t];
      if (tid < 100) sm->b1[tid] = b1_g[i * 100 + tid];
      const float* g = W2_g + i * 75000;     // (100,750); need cols u*15+p, p<3
      for (int t = tid; t < 15000; t += NTHREADS) {
        int h = t / 150;
        int c = t - h * 150;
        int u = c / 3;
        int p = c - u * 3;
        sm->W2[h][c] = g[h * 750 + u * 15 + p];
      }
    }
    __syncthreads();

    // ---- stage 1a: radial MLP hidden -> overlay in X slots 9/10 ----
    #pragma unroll
    for (int j = 0; j < 4; j++) {
      int h = ln + 32 * j;
      if (h < HIDC) {
        float a0 = 0.0f, a1 = 0.0f;
        #pragma unroll
        for (int b = 0; b < NBC; b++) {
          float w1 = sm->W1[b][h];
          a0 = fmaf(sm->emb[e0][b], w1, a0);
          a1 = fmaf(sm->emb[e1][b], w1, a1);
        }
        HID(e0, h) = geluf(a0 * 0.31622776601683794f + sm->b1[h]);
        HID(e1, h) = geluf(a1 * 0.31622776601683794f + sm->b1[h]);
      }
    }
    __syncwarp();

    // ---- stage 1b: wv[edge][ch][p] ----
    float wv[2][2][3] = {};
    if (act) {
      #pragma unroll 4
      for (int h = 0; h < HIDC; h++) {
        float h0v = HID(e0, h);
        float h1v = HID(e1, h);
        const float2* w2p = reinterpret_cast<const float2*>(&sm->W2[h][6 * ln]);
        float2 c0 = w2p[0], c1 = w2p[1], c2 = w2p[2];
        wv[0][0][0] = fmaf(h0v, c0.x, wv[0][0][0]);
        wv[0][0][1] = fmaf(h0v, c0.y, wv[0][0][1]);
        wv[0][0][2] = fmaf(h0v, c1.x, wv[0][0][2]);
        wv[0][1][0] = fmaf(h0v, c1.y, wv[0][1][0]);
        wv[0][1][1] = fmaf(h0v, c2.x, wv[0][1][1]);
        wv[0][1][2] = fmaf(h0v, c2.y, wv[0][1][2]);
        wv[1][0][0] = fmaf(h1v, c0.x, wv[1][0][0]);
        wv[1][0][1] = fmaf(h1v, c0.y, wv[1][0][1]);
        wv[1][0][2] = fmaf(h1v, c1.x, wv[1][0][2]);
        wv[1][1][0] = fmaf(h1v, c1.y, wv[1][1][0]);
        wv[1][1][1] = fmaf(h1v, c2.x, wv[1][1][1]);
        wv[1][1][2] = fmaf(h1v, c2.y, wv[1][1][2]);
      }
    }

    // ---- stage 2: source matvecs ----
    float h0a[2][2] = {};
    float sca[2][2] = {};
    if (act) {
      #pragma unroll 5
      for (int t = 0; t < MULC; t++) {
        float s0 = sm->s[e0][t];
        float s1 = sm->s[e1][t];
        float2 wl = *reinterpret_cast<const float2*>(&sm->Wl1[t][u0]);
        float2 ws = *reinterpret_cast<const float2*>(&sm->Wsc[0][t][u0]);
        h0a[0][0] = fmaf(s0, wl.x, h0a[0][0]);
        h0a[0][1] = fmaf(s0, wl.y, h0a[0][1]);
        sca[0][0] = fmaf(s0, ws.x, sca[0][0]);
        sca[0][1] = fmaf(s0, ws.y, sca[0][1]);
        h0a[1][0] = fmaf(s1, wl.x, h0a[1][0]);
        h0a[1][1] = fmaf(s1, wl.y, h0a[1][1]);
        sca[1][0] = fmaf(s1, ws.x, sca[1][0]);
        sca[1][1] = fmaf(s1, ws.y, sca[1][1]);
      }
    }
    __syncwarp();
    if (act) {
      #pragma unroll
      for (int e = 0; e < 2; e++) {
        int le = e0 + e;
        #pragma unroll
        for (int ch = 0; ch < 2; ch++) {
          int u = u0 + ch;
          float h0 = h0a[e][ch] * INVS50;
          float* xr = sm->X[le][u];
          xr[9]  = h0 * wv[e][ch][0] * 0.1f;
          xr[10] = h0 * wv[e][ch][1] * 0.1f;
          xr[11] = h0 * wv[e][ch][2] * 0.1f;
          sm->s[le][u] = siluf(CS * sca[e][ch] * INVS50);
        }
      }
    }
    __syncwarp();

    // ---- stage 3 ----
    float acc[2][2][9] = {};
    float bb[2][2][3] = {};
    if (act) {
      #pragma unroll 2
      for (int u = 0; u < MULC; u++) {
        const float4* x0p = reinterpret_cast<const float4*>(sm->X[e0][u]);
        float4 A0 = x0p[0], B0 = x0p[1], C0 = x0p[2];
        const float4* x1p = reinterpret_cast<const float4*>(sm->X[e1][u]);
        float4 A1 = x1p[0], B1 = x1p[1], C1 = x1p[2];
        float2 ws0 = *reinterpret_cast<const float2*>(&sm->Wsc[0][u][u0]);
        float2 ws1 = *reinterpret_cast<const float2*>(&sm->Wsc[1][u][u0]);
        float2 ws2 = *reinterpret_cast<const float2*>(&sm->Wsc[2][u][u0]);
        float2 l0 = *reinterpret_cast<const float2*>(&sm->Wl2[0][u][u0]);
        float2 l1 = *reinterpret_cast<const float2*>(&sm->Wl2[1][u][u0]);
        float2 l2 = *reinterpret_cast<const float2*>(&sm->Wl2[2][u][u0]);
        acc[0][0][0] = fmaf(A0.x, ws0.x, acc[0][0][0]);
        acc[0][0][1] = fmaf(A0.y, ws1.x, acc[0][0][1]);
        acc[0][0][2] = fmaf(A0.z, ws1.x, acc[0][0][2]);
        acc[0][0][3] = fmaf(A0.w, ws1.x, acc[0][0][3]);
        acc[0][0][4] = fmaf(B0.x, ws2.x, acc[0][0][4]);
        acc[0][0][5] = fmaf(B0.y, ws2.x, acc[0][0][5]);
        acc[0][0][6] = fmaf(B0.z, ws2.x, acc[0][0][6]);
        acc[0][0][7] = fmaf(B0.w, ws2.x, acc[0][0][7]);
        acc[0][0][8] = fmaf(C0.x, ws2.x, acc[0][0][8]);
        bb[0][0][0]  = fmaf(C0.y, l0.x, bb[0][0][0]);
        bb[0][0][1]  = fmaf(C0.z, l1.x, bb[0][0][1]);
        bb[0][0][2]  = fmaf(C0.w, l2.x, bb[0][0][2]);
        acc[0][1][0] = fmaf(A0.x, ws0.y, acc[0][1][0]);
        acc[0][1][1] = fmaf(A0.y, ws1.y, acc[0][1][1]);
        acc[0][1][2] = fmaf(A0.z, ws1.y, acc[0][1][2]);
        acc[0][1][3] = fmaf(A0.w, ws1.y, acc[0][1][3]);
        acc[0][1][4] = fmaf(B0.x, ws2.y, acc[0][1][4]);
        acc[0][1][5] = fmaf(B0.y, ws2.y, acc[0][1][5]);
        acc[0][1][6] = fmaf(B0.z, ws2.y, acc[0][1][6]);
        acc[0][1][7] = fmaf(B0.w, ws2.y, acc[0][1][7]);
        acc[0][1][8] = fmaf(C0.x, ws2.y, acc[0][1][8]);
        bb[0][1][0]  = fmaf(C0.y, l0.y, bb[0][1][0]);
        bb[0][1][1]  = fmaf(C0.z, l1.y, bb[0][1][1]);
        bb[0][1][2]  = fmaf(C0.w, l2.y, bb[0][1][2]);
        acc[1][0][0] = fmaf(A1.x, ws0.x, acc[1][0][0]);
        acc[1][0][1] = fmaf(A1.y, ws1.x, acc[1][0][1]);
        acc[1][0][2] = fmaf(A1.z, ws1.x, acc[1][0][2]);
        acc[1][0][3] = fmaf(A1.w, ws1.x, acc[1][0][3]);
        acc[1][0][4] = fmaf(B1.x, ws2.x, acc[1][0][4]);
        acc[1][0][5] = fmaf(B1.y, ws2.x, acc[1][0][5]);
        acc[1][0][6] = fmaf(B1.z, ws2.x, acc[1][0][6]);
        acc[1][0][7] = fmaf(B1.w, ws2.x, acc[1][0][7]);
        acc[1][0][8] = fmaf(C1.x, ws2.x, acc[1][0][8]);
        bb[1][0][0]  = fmaf(C1.y, l0.x, bb[1][0][0]);
        bb[1][0][1]  = fmaf(C1.z, l1.x, bb[1][0][1]);
        bb[1][0][2]  = fmaf(C1.w, l2.x, bb[1][0][2]);
        acc[1][1][0] = fmaf(A1.x, ws0.y, acc[1][1][0]);
        acc[1][1][1] = fmaf(A1.y, ws1.y, acc[1][1][1]);
        acc[1][1][2] = fmaf(A1.z, ws1.y, acc[1][1][2]);
        acc[1][1][3] = fmaf(A1.w, ws1.y, acc[1][1][3]);
        acc[1][1][4] = fmaf(B1.x, ws2.y, acc[1][1][4]);
        acc[1][1][5] = fmaf(B1.y, ws2.y, acc[1][1][5]);
        acc[1][1][6] = fmaf(B1.z, ws2.y, acc[1][1][6]);
        acc[1][1][7] = fmaf(B1.w, ws2.y, acc[1][1][7]);
        acc[1][1][8] = fmaf(C1.x, ws2.y, acc[1][1][8]);
        bb[1][1][0]  = fmaf(C1.y, l0.y, bb[1][1][0]);
        bb[1][1][1]  = fmaf(C1.z, l1.y, bb[1][1][1]);
        bb[1][1][2]  = fmaf(C1.w, l2.y, bb[1][1][2]);
      }
    }
    __syncwarp();   // all lanes done reading X
    if (act) {
      #pragma unroll
      for (int e = 0; e < 2; e++) {
        int le = e0 + e;
        const float* shl = sm->shv[le];
        #pragma unroll
        for (int ch = 0; ch < 2; ch++) {
          int u = u0 + ch;
          float* xr = sm->X[le][u];
          xr[0] = CS * INVS50 * acc[e][ch][0] + CXK0 * bb[e][ch][0];
          #pragma unroll
          for (int k = 1; k < 4; k++)
            xr[k] = CS * INVS50 * acc[e][ch][k] + CXK1 * bb[e][ch][1] * shl[k];
          #pragma unroll
          for (int k = 4; k < 9; k++)
            xr[k] = CS * INVS50 * acc[e][ch][k] + CXK2 * bb[e][ch][2] * shl[k];
        }
      }
    }
    __syncwarp();

    // ---- stage 4: gate ----
    float ga[2][2] = {};
    if (act) {
      #pragma unroll 5
      for (int u = 0; u < MULC; u++) {
        float t0 = sm->X[e0][u][0];
        float t1 = sm->X[e1][u][0];
        float2 wg = *reinterpret_cast<const float2*>(&sm->Wg[u][u0]);
        ga[0][0] = fmaf(t0, wg.x, ga[0][0]);
        ga[0][1] = fmaf(t0, wg.y, ga[0][1]);
        ga[1][0] = fmaf(t1, wg.x, ga[1][0]);
        ga[1][1] = fmaf(t1, wg.y, ga[1][1]);
      }
    }
    __syncwarp();
    if (act) {
      #pragma unroll
      for (int e = 0; e < 2; e++) {
        int le = e0 + e;
        #pragma unroll
        for (int ch = 0; ch < 2; ch++) {
          int u = u0 + ch;
          float g = sigmoidf(ga[e][ch] * INVS50);
          float* xr = sm->X[le][u];
          float4 A = *reinterpret_cast<const float4*>(xr);
          float4 B = *reinterpret_cast<const float4*>(xr + 4);
          float x8 = xr[8];
          float4 qa = make_float4(siluf(A.x), A.y * g, A.z * g, A.w * g);
          float4 qb = make_float4(B.x * g, B.y * g, B.z * g, B.w * g);
          *reinterpret_cast<float4*>(xr)     = qa;
          *reinterpret_cast<float4*>(xr + 4) = qb;
          xr[8] = x8 * g;
        }
      }
    }
    __syncwarp();
  }

  // ---------------- output ----------------
  {
    float p[2][3] = {};
    if (act) {
      float wo0 = Wout_g[u0];
      float wo1 = Wout_g[u0 + 1];
      #pragma unroll
      for (int e = 0; e < 2; e++) {
        int le = e0 + e;
        const float* r0 = sm->X[le][u0];
        const float* r1 = sm->X[le][u0 + 1];
        p[e][0] = r0[1] * wo0 + r1[1] * wo1;
        p[e][1] = r0[2] * wo0 + r1[2] * wo1;
        p[e][2] = r0[3] * wo0 + r1[3] * wo1;
      }
    }
    #pragma unroll
    for (int off = 16; off; off >>= 1) {
      #pragma unroll
      for (int e = 0; e < 2; e++) {
        p[e][0] += __shfl_xor_sync(0xffffffffu, p[e][0], off);
        p[e][1] += __shfl_xor_sync(0xffffffffu, p[e][1], off);
        p[e][2] += __shfl_xor_sync(0xffffffffu, p[e][2], off);
      }
    }
    if (ln == 0) {
      int eg0 = blockIdx.x * TE + e0;
      float* od = out + (size_t)(2 * eg0) * 3;
      od[0] = 0.0f; od[1] = 0.0f; od[2] = 0.0f;
      od[3] = p[0][0] * INVS50;
      od[4] = p[0][1] * INVS50;
      od[5] = p[0][2] * INVS50;
      od[6] = 0.0f; od[7] = 0.0f; od[8] = 0.0f;
      od[9]  = p[1][0] * INVS50;
      od[10] = p[1][1] * INVS50;
      od[11] = p[1][2] * INVS50;
    }
  }
}

extern "C" void kernel_launch(void* const* d_in, const int* in_sizes, int n_in,
                              void* d_out, int out_size) {
  const float* node_pos = (const float*)d_in[0];
  const float* bar_alpha = (const float*)d_in[1];
  const float* W_embed  = (const float*)d_in[2];
  const float* Wsc      = (const float*)d_in[3];
  const float* Wlin1    = (const float*)d_in[4];
  const float* W1       = (const float*)d_in[5];
  const float* b1       = (const float*)d_in[6];
  const float* W2       = (const float*)d_in[7];
  const float* Wlin2    = (const float*)d_in[8];
  const float* Wgate    = (const float*)d_in[9];
  const float* W_out    = (const float*)d_in[10];
  float* out = (float*)d_out;

  int E = in_sizes[0] / 6;          // 40000, divisible by TE=32? 40000/32=1250 yes
  size_t smem = sizeof(SM);
  cudaFuncSetAttribute(slinky_kernel, cudaFuncAttributeMaxDynamicSharedMemorySize, (int)smem);
  slinky_kernel<<<E / TE, NTHREADS, smem>>>(node_pos, bar_alpha, W_embed, Wsc, Wlin1,
                                            W1, b1, W2, Wlin2, Wgate, W_out, out);
}

// round 5
// speedup vs baseline: 1.6867x; 1.0782x over previous
#include <cuda_runtime.h>
#include <cuda_fp16.h>

// SlinkyForcePredictor — fused per-edge kernel, v4.
// v3 was L1-crossbar-bound (80.2%), weight LDS = 2/3 of wavefronts.
// v4: weights stored as fp16 in SMEM (math stays fp32) -> weight rows are
//     100B = 1 wavefront instead of 2. Everything else identical to v3.

#define MULC 50
#define NBC 10
#define HIDC 100
#define TE 32
#define NTHREADS 512

struct SM {
  float X[TE][MULC][12];      // slots 0..8 = x; 9..11 = hid overlay then a0..a2
  float s[TE][MULC];
  float shv[TE][12];
  float emb[TE][12];
  __half Wsc[3][MULC][MULC];
  __half Wl1[MULC][MULC];
  __half Wl2[3][MULC][MULC];
  __half Wg[MULC][MULC];
  float W1[NBC][HIDC];
  float b1[104];
  __half W2[HIDC][152];       // [h][u*3+p]
};

#define HID(le,h) sm->X[le][(h) >> 1][9 + ((h) & 1)]

__device__ __forceinline__ float geluf(float x) {
  float x3 = x * x * x;
  float t = tanhf(0.7978845608028654f * (x + 0.044715f * x3));
  return 0.5f * x * (1.0f + t);
}
__device__ __forceinline__ float sigmoidf(float x) { return 1.0f / (1.0f + expf(-x)); }
__device__ __forceinline__ float siluf(float x) { return x * sigmoidf(x); }

__device__ __forceinline__ float2 ldh2(const __half* p) {
  return __half22float2(*reinterpret_cast<const __half2*>(p));
}

__global__ __launch_bounds__(NTHREADS, 1)
void slinky_kernel(const float* __restrict__ node_pos,
                   const float* __restrict__ bar_alpha,
                   const float* __restrict__ W_embed,
                   const float* __restrict__ Wsc_g,
                   const float* __restrict__ Wlin1_g,
                   const float* __restrict__ W1_g,
                   const float* __restrict__ b1_g,
                   const float* __restrict__ W2_g,
                   const float* __restrict__ Wlin2_g,
                   const float* __restrict__ Wgate_g,
                   const float* __restrict__ Wout_g,
                   float* __restrict__ out)
{
  extern __shared__ __align__(16) float smem_raw[];
  SM* sm = reinterpret_cast<SM*>(smem_raw);

  const int tid = threadIdx.x;
  const int w   = tid >> 5;
  const int ln  = tid & 31;
  const int e0  = 2 * w;
  const int e1  = 2 * w + 1;
  const bool act = (ln < 25);
  const int u0 = 2 * ln;

  const float INVS50 = 0.1414213562373095f;
  const float CS = 0.9238795325112867f;
  const float CX = 0.3826834323650898f;
  const float CXK0 = CX * 0.05773502691896258f;
  const float CXK1 = CX * 0.02357022603955159f;
  const float CXK2 = CX * 0.01825741858350554f;

  // ---------------- preprocess ----------------
  {
    const int half = ln >> 4;
    const int l16 = ln & 15;
    const int le = e0 + half;
    const int eg = blockIdx.x * TE + le;
    const float* p6 = node_pos + (size_t)eg * 6;
    float ex = p6[1] - p6[0];
    float ey = p6[3] - p6[2];
    float ez = p6[5] - p6[4];
    float r = sqrtf(ex * ex + ey * ey + ez * ez);
    float inv = 1.0f / fmaxf(r, 1e-12f);
    float vx = ex * inv, vy = ey * inv, vz = ez * inv;
    if (l16 == 0) {
      const float s3 = 1.7320508075688772f;
      const float s5 = 2.23606797749979f;
      const float s15 = 3.872983346207417f;
      float* shp = sm->shv[le];
      shp[0] = 1.0f;
      shp[1] = s3 * vx;
      shp[2] = s3 * vy;
      shp[3] = s3 * vz;
      shp[4] = s15 * vx * vz;
      shp[5] = s15 * vx * vy;
      shp[6] = s5 * (vy * vy - 0.5f * (vx * vx + vz * vz));
      shp[7] = s15 * vy * vz;
      shp[8] = 0.5f * s15 * (vz * vz - vx * vx);
    }
    if (l16 < NBC) {
      const float step = 4.0f / 11.0f;
      float c = (float)(l16 + 1) * step;
      float diff = (r - c) / step;
      float up = diff + 1.0f, um = 1.0f - diff;
      float ua = (up > 0.0f) ? expf(-1.0f / up) : 0.0f;
      float ub = (um > 0.0f) ? expf(-1.0f / um) : 0.0f;
      sm->emb[le][l16] = (1.14136f * 7.3890560989306495f * 3.1622776601683795f) * ua * ub;
    }
  }
  if (act) {
    const int geb = blockIdx.x * TE;
    #pragma unroll
    for (int e = 0; e < 2; e++) {
      int le = e0 + e;
      int eg = geb + le;
      float ba_s = bar_alpha[2 * eg];
      float ba_d = bar_alpha[2 * eg + 1];
      #pragma unroll
      for (int ch = 0; ch < 2; ch++) {
        int u = u0 + ch;
        float we = W_embed[u];
        sm->s[le][u] = ba_s * we;
        float* xr = sm->X[le][u];
        xr[0] = ba_d * we;
        #pragma unroll
        for (int k = 1; k < 9; k++) xr[k] = 0.0f;
      }
    }
  }

  // ---------------- layers ----------------
  for (int i = 0; i < 3; i++) {
    __syncthreads();
    // cooperative weight staging: fp32 global -> fp16 smem
    {
      const float2* g2 = reinterpret_cast<const float2*>(Wsc_g + i * 7500);
      __half2* dh = reinterpret_cast<__half2*>(&sm->Wsc[0][0][0]);
      for (int t = tid; t < 3750; t += NTHREADS) dh[t] = __float22half2_rn(g2[t]);
      g2 = reinterpret_cast<const float2*>(Wlin1_g + i * 7500);
      dh = reinterpret_cast<__half2*>(&sm->Wl1[0][0]);
      for (int t = tid; t < 1250; t += NTHREADS) dh[t] = __float22half2_rn(g2[t]);
      g2 = reinterpret_cast<const float2*>(Wlin2_g + i * 7500);
      dh = reinterpret_cast<__half2*>(&sm->Wl2[0][0][0]);
      for (int t = tid; t < 3750; t += NTHREADS) dh[t] = __float22half2_rn(g2[t]);
      g2 = reinterpret_cast<const float2*>(Wgate_g + i * 2500);
      dh = reinterpret_cast<__half2*>(&sm->Wg[0][0]);
      for (int t = tid; t < 1250; t += NTHREADS) dh[t] = __float22half2_rn(g2[t]);
      const float4* g4 = reinterpret_cast<const float4*>(W1_g + i * 1000);
      float4* d4 = reinterpret_cast<float4*>(&sm->W1[0][0]);
      for (int t = tid; t < 250; t += NTHREADS) d4[t] = g4[t];
      if (tid < 100) sm->b1[tid] = b1_g[i * 100 + tid];
      const float* g = W2_g + i * 75000;     // (100,750); need cols u*15+p, p<3
      for (int t = tid; t < 15000; t += NTHREADS) {
        int h = t / 150;
        int c = t - h * 150;
        int u = c / 3;
        int p = c - u * 3;
        sm->W2[h][c] = __float2half_rn(g[h * 750 + u * 15 + p]);
      }
    }
    __syncthreads();

    // ---- stage 1a: radial MLP hidden -> overlay in X slots 9/10 ----
    #pragma unroll
    for (int j = 0; j < 4; j++) {
      int h = ln + 32 * j;
      if (h < HIDC) {
        float a0 = 0.0f, a1 = 0.0f;
        #pragma unroll
        for (int b = 0; b < NBC; b++) {
          float w1 = sm->W1[b][h];
          a0 = fmaf(sm->emb[e0][b], w1, a0);
          a1 = fmaf(sm->emb[e1][b], w1, a1);
        }
        HID(e0, h) = geluf(a0 * 0.31622776601683794f + sm->b1[h]);
        HID(e1, h) = geluf(a1 * 0.31622776601683794f + sm->b1[h]);
      }
    }
    __syncwarp();

    // ---- stage 1b: wv[edge][ch][p] ----
    float wv[2][2][3] = {};
    if (act) {
      #pragma unroll 4
      for (int h = 0; h < HIDC; h++) {
        float h0v = HID(e0, h);
        float h1v = HID(e1, h);
        const __half* w2p = &sm->W2[h][6 * ln];
        float2 c0 = ldh2(w2p), c1 = ldh2(w2p + 2), c2 = ldh2(w2p + 4);
        wv[0][0][0] = fmaf(h0v, c0.x, wv[0][0][0]);
        wv[0][0][1] = fmaf(h0v, c0.y, wv[0][0][1]);
        wv[0][0][2] = fmaf(h0v, c1.x, wv[0][0][2]);
        wv[0][1][0] = fmaf(h0v, c1.y, wv[0][1][0]);
        wv[0][1][1] = fmaf(h0v, c2.x, wv[0][1][1]);
        wv[0][1][2] = fmaf(h0v, c2.y, wv[0][1][2]);
        wv[1][0][0] = fmaf(h1v, c0.x, wv[1][0][0]);
        wv[1][0][1] = fmaf(h1v, c0.y, wv[1][0][1]);
        wv[1][0][2] = fmaf(h1v, c1.x, wv[1][0][2]);
        wv[1][1][0] = fmaf(h1v, c1.y, wv[1][1][0]);
        wv[1][1][1] = fmaf(h1v, c2.x, wv[1][1][1]);
        wv[1][1][2] = fmaf(h1v, c2.y, wv[1][1][2]);
      }
    }

    // ---- stage 2: source matvecs ----
    float h0a[2][2] = {};
    float sca[2][2] = {};
    if (act) {
      #pragma unroll 5
      for (int t = 0; t < MULC; t++) {
        float s0 = sm->s[e0][t];
        float s1 = sm->s[e1][t];
        float2 wl = ldh2(&sm->Wl1[t][u0]);
        float2 ws = ldh2(&sm->Wsc[0][t][u0]);
        h0a[0][0] = fmaf(s0, wl.x, h0a[0][0]);
        h0a[0][1] = fmaf(s0, wl.y, h0a[0][1]);
        sca[0][0] = fmaf(s0, ws.x, sca[0][0]);
        sca[0][1] = fmaf(s0, ws.y, sca[0][1]);
        h0a[1][0] = fmaf(s1, wl.x, h0a[1][0]);
        h0a[1][1] = fmaf(s1, wl.y, h0a[1][1]);
        sca[1][0] = fmaf(s1, ws.x, sca[1][0]);
        sca[1][1] = fmaf(s1, ws.y, sca[1][1]);
      }
    }
    __syncwarp();
    if (act) {
      #pragma unroll
      for (int e = 0; e < 2; e++) {
        int le = e0 + e;
        #pragma unroll
        for (int ch = 0; ch < 2; ch++) {
          int u = u0 + ch;
          float h0 = h0a[e][ch] * INVS50;
          float* xr = sm->X[le][u];
          xr[9]  = h0 * wv[e][ch][0] * 0.1f;
          xr[10] = h0 * wv[e][ch][1] * 0.1f;
          xr[11] = h0 * wv[e][ch][2] * 0.1f;
          sm->s[le][u] = siluf(CS * sca[e][ch] * INVS50);
        }
      }
    }
    __syncwarp();

    // ---- stage 3 ----
    float acc[2][2][9] = {};
    float bb[2][2][3] = {};
    if (act) {
      #pragma unroll 2
      for (int u = 0; u < MULC; u++) {
        const float4* x0p = reinterpret_cast<const float4*>(sm->X[e0][u]);
        float4 A0 = x0p[0], B0 = x0p[1], C0 = x0p[2];
        const float4* x1p = reinterpret_cast<const float4*>(sm->X[e1][u]);
        float4 A1 = x1p[0], B1 = x1p[1], C1 = x1p[2];
        float2 ws0 = ldh2(&sm->Wsc[0][u][u0]);
        float2 ws1 = ldh2(&sm->Wsc[1][u][u0]);
        float2 ws2 = ldh2(&sm->Wsc[2][u][u0]);
        float2 l0 = ldh2(&sm->Wl2[0][u][u0]);
        float2 l1 = ldh2(&sm->Wl2[1][u][u0]);
        float2 l2 = ldh2(&sm->Wl2[2][u][u0]);
        acc[0][0][0] = fmaf(A0.x, ws0.x, acc[0][0][0]);
        acc[0][0][1] = fmaf(A0.y, ws1.x, acc[0][0][1]);
        acc[0][0][2] = fmaf(A0.z, ws1.x, acc[0][0][2]);
        acc[0][0][3] = fmaf(A0.w, ws1.x, acc[0][0][3]);
        acc[0][0][4] = fmaf(B0.x, ws2.x, acc[0][0][4]);
        acc[0][0][5] = fmaf(B0.y, ws2.x, acc[0][0][5]);
        acc[0][0][6] = fmaf(B0.z, ws2.x, acc[0][0][6]);
        acc[0][0][7] = fmaf(B0.w, ws2.x, acc[0][0][7]);
        acc[0][0][8] = fmaf(C0.x, ws2.x, acc[0][0][8]);
        bb[0][0][0]  = fmaf(C0.y, l0.x, bb[0][0][0]);
        bb[0][0][1]  = fmaf(C0.z, l1.x, bb[0][0][1]);
        bb[0][0][2]  = fmaf(C0.w, l2.x, bb[0][0][2]);
        acc[0][1][0] = fmaf(A0.x, ws0.y, acc[0][1][0]);
        acc[0][1][1] = fmaf(A0.y, ws1.y, acc[0][1][1]);
        acc[0][1][2] = fmaf(A0.z, ws1.y, acc[0][1][2]);
        acc[0][1][3] = fmaf(A0.w, ws1.y, acc[0][1][3]);
        acc[0][1][4] = fmaf(B0.x, ws2.y, acc[0][1][4]);
        acc[0][1][5] = fmaf(B0.y, ws2.y, acc[0][1][5]);
        acc[0][1][6] = fmaf(B0.z, ws2.y, acc[0][1][6]);
        acc[0][1][7] = fmaf(B0.w, ws2.y, acc[0][1][7]);
        acc[0][1][8] = fmaf(C0.x, ws2.y, acc[0][1][8]);
        bb[0][1][0]  = fmaf(C0.y, l0.y, bb[0][1][0]);
        bb[0][1][1]  = fmaf(C0.z, l1.y, bb[0][1][1]);
        bb[0][1][2]  = fmaf(C0.w, l2.y, bb[0][1][2]);
        acc[1][0][0] = fmaf(A1.x, ws0.x, acc[1][0][0]);
        acc[1][0][1] = fmaf(A1.y, ws1.x, acc[1][0][1]);
        acc[1][0][2] = fmaf(A1.z, ws1.x, acc[1][0][2]);
        acc[1][0][3] = fmaf(A1.w, ws1.x, acc[1][0][3]);
        acc[1][0][4] = fmaf(B1.x, ws2.x, acc[1][0][4]);
        acc[1][0][5] = fmaf(B1.y, ws2.x, acc[1][0][5]);
        acc[1][0][6] = fmaf(B1.z, ws2.x, acc[1][0][6]);
        acc[1][0][7] = fmaf(B1.w, ws2.x, acc[1][0][7]);
        acc[1][0][8] = fmaf(C1.x, ws2.x, acc[1][0][8]);
        bb[1][0][0]  = fmaf(C1.y, l0.x, bb[1][0][0]);
        bb[1][0][1]  = fmaf(C1.z, l1.x, bb[1][0][1]);
        bb[1][0][2]  = fmaf(C1.w, l2.x, bb[1][0][2]);
        acc[1][1][0] = fmaf(A1.x, ws0.y, acc[1][1][0]);
        acc[1][1][1] = fmaf(A1.y, ws1.y, acc[1][1][1]);
        acc[1][1][2] = fmaf(A1.z, ws1.y, acc[1][1][2]);
        acc[1][1][3] = fmaf(A1.w, ws1.y, acc[1][1][3]);
        acc[1][1][4] = fmaf(B1.x, ws2.y, acc[1][1][4]);
        acc[1][1][5] = fmaf(B1.y, ws2.y, acc[1][1][5]);
        acc[1][1][6] = fmaf(B1.z, ws2.y, acc[1][1][6]);
        acc[1][1][7] = fmaf(B1.w, ws2.y, acc[1][1][7]);
        acc[1][1][8] = fmaf(C1.x, ws2.y, acc[1][1][8]);
        bb[1][1][0]  = fmaf(C1.y, l0.y, bb[1][1][0]);
        bb[1][1][1]  = fmaf(C1.z, l1.y, bb[1][1][1]);
        bb[1][1][2]  = fmaf(C1.w, l2.y, bb[1][1][2]);
      }
    }
    __syncwarp();
    if (act) {
      #pragma unroll
      for (int e = 0; e < 2; e++) {
        int le = e0 + e;
        const float* shl = sm->shv[le];
        #pragma unroll
        for (int ch = 0; ch < 2; ch++) {
          int u = u0 + ch;
          float* xr = sm->X[le][u];
          xr[0] = CS * INVS50 * acc[e][ch][0] + CXK0 * bb[e][ch][0];
          #pragma unroll
          for (int k = 1; k < 4; k++)
            xr[k] = CS * INVS50 * acc[e][ch][k] + CXK1 * bb[e][ch][1] * shl[k];
          #pragma unroll
          for (int k = 4; k < 9; k++)
            xr[k] = CS * INVS50 * acc[e][ch][k] + CXK2 * bb[e][ch][2] * shl[k];
        }
      }
    }
    __syncwarp();

    // ---- stage 4: gate ----
    float ga[2][2] = {};
    if (act) {
      #pragma unroll 5
      for (int u = 0; u < MULC; u++) {
        float t0 = sm->X[e0][u][0];
        float t1 = sm->X[e1][u][0];
        float2 wg = ldh2(&sm->Wg[u][u0]);
        ga[0][0] = fmaf(t0, wg.x, ga[0][0]);
        ga[0][1] = fmaf(t0, wg.y, ga[0][1]);
        ga[1][0] = fmaf(t1, wg.x, ga[1][0]);
        ga[1][1] = fmaf(t1, wg.y, ga[1][1]);
      }
    }
    __syncwarp();
    if (act) {
      #pragma unroll
      for (int e = 0; e < 2; e++) {
        int le = e0 + e;
        #pragma unroll
        for (int ch = 0; ch < 2; ch++) {
          int u = u0 + ch;
          float g = sigmoidf(ga[e][ch] * INVS50);
          float* xr = sm->X[le][u];
          float4 A = *reinterpret_cast<const float4*>(xr);
          float4 B = *reinterpret_cast<const float4*>(xr + 4);
          float x8 = xr[8];
          float4 qa = make_float4(siluf(A.x), A.y * g, A.z * g, A.w * g);
          float4 qb = make_float4(B.x * g, B.y * g, B.z * g, B.w * g);
          *reinterpret_cast<float4*>(xr)     = qa;
          *reinterpret_cast<float4*>(xr + 4) = qb;
          xr[8] = x8 * g;
        }
      }
    }
    __syncwarp();
  }

  // ---------------- output ----------------
  {
    float p[2][3] = {};
    if (act) {
      float wo0 = Wout_g[u0];
      float wo1 = Wout_g[u0 + 1];
      #pragma unroll
      for (int e = 0; e < 2; e++) {
        int le = e0 + e;
        const float* r0 = sm->X[le][u0];
        const float* r1 = sm->X[le][u0 + 1];
        p[e][0] = r0[1] * wo0 + r1[1] * wo1;
        p[e][1] = r0[2] * wo0 + r1[2] * wo1;
        p[e][2] = r0[3] * wo0 + r1[3] * wo1;
      }
    }
    #pragma unroll
    for (int off = 16; off; off >>= 1) {
      #pragma unroll
      for (int e = 0; e < 2; e++) {
        p[e][0] += __shfl_xor_sync(0xffffffffu, p[e][0], off);
        p[e][1] += __shfl_xor_sync(0xffffffffu, p[e][1], off);
        p[e][2] += __shfl_xor_sync(0xffffffffu, p[e][2], off);
      }
    }
    if (ln == 0) {
      int eg0 = blockIdx.x * TE + e0;
      float* od = out + (size_t)(2 * eg0) * 3;
      od[0] = 0.0f; od[1] = 0.0f; od[2] = 0.0f;
      od[3] = p[0][0] * INVS50;
      od[4] = p[0][1] * INVS50;
      od[5] = p[0][2] * INVS50;
      od[6] = 0.0f; od[7] = 0.0f; od[8] = 0.0f;
      od[9]  = p[1][0] * INVS50;
      od[10] = p[1][1] * INVS50;
      od[11] = p[1][2] * INVS50;
    }
  }
}

extern "C" void kernel_launch(void* const* d_in, const int* in_sizes, int n_in,
                              void* d_out, int out_size) {
  const float* node_pos = (const float*)d_in[0];
  const float* bar_alpha = (const float*)d_in[1];
  const float* W_embed  = (const float*)d_in[2];
  const float* Wsc      = (const float*)d_in[3];
  const float* Wlin1    = (const float*)d_in[4];
  const float* W1       = (const float*)d_in[5];
  const float* b1       = (const float*)d_in[6];
  const float* W2       = (const float*)d_in[7];
  const float* Wlin2    = (const float*)d_in[8];
  const float* Wgate    = (const float*)d_in[9];
  const float* W_out    = (const float*)d_in[10];
  float* out = (float*)d_out;

  int E = in_sizes[0] / 6;          // 40000, /32 = 1250 blocks
  size_t smem = sizeof(SM);
  cudaFuncSetAttribute(slinky_kernel, cudaFuncAttributeMaxDynamicSharedMemorySize, (int)smem);
  slinky_kernel<<<E / TE, NTHREADS, smem>>>(node_pos, bar_alpha, W_embed, Wsc, Wlin1,
                                            W1, b1, W2, Wlin2, Wgate, W_out, out);
}

// round 6
// speedup vs baseline: 1.7064x; 1.0117x over previous
#include <cuda_runtime.h>
#include <cuda_fp16.h>

// SlinkyForcePredictor — fused per-edge kernel, v5.
// v4 was issue-slot limited (issue 67.7%, fma 44.3%, L1 65%).
// v5: packed fp32 math via PTX fma.rn.f32x2 (SASS FFMA2, 2 FMAs/instr).
//     X row layout permuted to [x1,x2,x3,x0,x4..x8,a0,a1,a2] so all 12 slots
//     form 6 pairable f32x2 operands sharing packed weights.

#define MULC 50
#define NBC 10
#define HIDC 100
#define TE 32
#define NTHREADS 512

typedef unsigned long long u64;

struct SM {
  float X[TE][MULC][12];      // phys: [x1,x2,x3,x0,x4,x5,x6,x7,x8,a0,a1,a2]
  float s[TE][MULC];
  float shv[TE][12];
  float emb[TE][12];
  __half Wsc[3][MULC][MULC];
  __half Wl1[MULC][MULC];
  __half Wl2[3][MULC][MULC];
  __half Wg[MULC][MULC];
  float W1[NBC][HIDC];
  float b1[104];
  __half W2[HIDC][152];       // [h][u*3+p]
};

#define HID(le,h) sm->X[le][(h) >> 1][9 + ((h) & 1)]

__device__ __forceinline__ float geluf(float x) {
  float x3 = x * x * x;
  float t = tanhf(0.7978845608028654f * (x + 0.044715f * x3));
  return 0.5f * x * (1.0f + t);
}
__device__ __forceinline__ float sigmoidf(float x) { return 1.0f / (1.0f + expf(-x)); }
__device__ __forceinline__ float siluf(float x) { return x * sigmoidf(x); }

__device__ __forceinline__ float2 ldh2(const __half* p) {
  return __half22float2(*reinterpret_cast<const __half2*>(p));
}
__device__ __forceinline__ u64 pk(float lo, float hi) {
  u64 r; asm("mov.b64 %0, {%1, %2};" : "=l"(r) : "f"(lo), "f"(hi)); return r;
}
__device__ __forceinline__ void upk(float& lo, float& hi, u64 v) {
  asm("mov.b64 {%0, %1}, %2;" : "=f"(lo), "=f"(hi) : "l"(v));
}
__device__ __forceinline__ void fma2(u64& d, u64 a, u64 b) {
  asm("fma.rn.f32x2 %0, %1, %2, %3;" : "=l"(d) : "l"(a), "l"(b), "l"(d));
}

__global__ __launch_bounds__(NTHREADS, 1)
void slinky_kernel(const float* __restrict__ node_pos,
                   const float* __restrict__ bar_alpha,
                   const float* __restrict__ W_embed,
                   const float* __restrict__ Wsc_g,
                   const float* __restrict__ Wlin1_g,
                   const float* __restrict__ W1_g,
                   const float* __restrict__ b1_g,
                   const float* __restrict__ W2_g,
                   const float* __restrict__ Wlin2_g,
                   const float* __restrict__ Wgate_g,
                   const float* __restrict__ Wout_g,
                   float* __restrict__ out)
{
  extern __shared__ __align__(16) float smem_raw[];
  SM* sm = reinterpret_cast<SM*>(smem_raw);

  const int tid = threadIdx.x;
  const int w   = tid >> 5;
  const int ln  = tid & 31;
  const int e0  = 2 * w;
  const int e1  = 2 * w + 1;
  const bool act = (ln < 25);
  const int u0 = 2 * ln;

  const float INVS50 = 0.1414213562373095f;
  const float CS = 0.9238795325112867f;
  const float CX = 0.3826834323650898f;
  const float CXK0 = CX * 0.05773502691896258f;
  const float CXK1 = CX * 0.02357022603955159f;
  const float CXK2 = CX * 0.01825741858350554f;

  // ---------------- preprocess ----------------
  {
    const int half = ln >> 4;
    const int l16 = ln & 15;
    const int le = e0 + half;
    const int eg = blockIdx.x * TE + le;
    const float* p6 = node_pos + (size_t)eg * 6;
    float ex = p6[1] - p6[0];
    float ey = p6[3] - p6[2];
    float ez = p6[5] - p6[4];
    float r = sqrtf(ex * ex + ey * ey + ez * ez);
    float inv = 1.0f / fmaxf(r, 1e-12f);
    float vx = ex * inv, vy = ey * inv, vz = ez * inv;
    if (l16 == 0) {
      const float s3 = 1.7320508075688772f;
      const float s5 = 2.23606797749979f;
      const float s15 = 3.872983346207417f;
      float* shp = sm->shv[le];
      shp[0] = 1.0f;
      shp[1] = s3 * vx;
      shp[2] = s3 * vy;
      shp[3] = s3 * vz;
      shp[4] = s15 * vx * vz;
      shp[5] = s15 * vx * vy;
      shp[6] = s5 * (vy * vy - 0.5f * (vx * vx + vz * vz));
      shp[7] = s15 * vy * vz;
      shp[8] = 0.5f * s15 * (vz * vz - vx * vx);
    }
    if (l16 < NBC) {
      const float step = 4.0f / 11.0f;
      float c = (float)(l16 + 1) * step;
      float diff = (r - c) / step;
      float up = diff + 1.0f, um = 1.0f - diff;
      float ua = (up > 0.0f) ? expf(-1.0f / up) : 0.0f;
      float ub = (um > 0.0f) ? expf(-1.0f / um) : 0.0f;
      sm->emb[le][l16] = (1.14136f * 7.3890560989306495f * 3.1622776601683795f) * ua * ub;
    }
  }
  if (act) {
    const int geb = blockIdx.x * TE;
    #pragma unroll
    for (int e = 0; e < 2; e++) {
      int le = e0 + e;
      int eg = geb + le;
      float ba_s = bar_alpha[2 * eg];
      float ba_d = bar_alpha[2 * eg + 1];
      #pragma unroll
      for (int ch = 0; ch < 2; ch++) {
        int u = u0 + ch;
        float we = W_embed[u];
        sm->s[le][u] = ba_s * we;
        float* xr = sm->X[le][u];
        xr[0] = 0.0f; xr[1] = 0.0f; xr[2] = 0.0f;
        xr[3] = ba_d * we;                        // x0 lives at phys 3
        xr[4] = 0.0f; xr[5] = 0.0f; xr[6] = 0.0f; xr[7] = 0.0f; xr[8] = 0.0f;
      }
    }
  }

  // ---------------- layers ----------------
  for (int i = 0; i < 3; i++) {
    __syncthreads();
    // weight staging: fp32 global -> fp16 smem
    {
      const float2* g2 = reinterpret_cast<const float2*>(Wsc_g + i * 7500);
      __half2* dh = reinterpret_cast<__half2*>(&sm->Wsc[0][0][0]);
      for (int t = tid; t < 3750; t += NTHREADS) dh[t] = __float22half2_rn(g2[t]);
      g2 = reinterpret_cast<const float2*>(Wlin1_g + i * 7500);
      dh = reinterpret_cast<__half2*>(&sm->Wl1[0][0]);
      for (int t = tid; t < 1250; t += NTHREADS) dh[t] = __float22half2_rn(g2[t]);
      g2 = reinterpret_cast<const float2*>(Wlin2_g + i * 7500);
      dh = reinterpret_cast<__half2*>(&sm->Wl2[0][0][0]);
      for (int t = tid; t < 3750; t += NTHREADS) dh[t] = __float22half2_rn(g2[t]);
      g2 = reinterpret_cast<const float2*>(Wgate_g + i * 2500);
      dh = reinterpret_cast<__half2*>(&sm->Wg[0][0]);
      for (int t = tid; t < 1250; t += NTHREADS) dh[t] = __float22half2_rn(g2[t]);
      const float4* g4 = reinterpret_cast<const float4*>(W1_g + i * 1000);
      float4* d4 = reinterpret_cast<float4*>(&sm->W1[0][0]);
      for (int t = tid; t < 250; t += NTHREADS) d4[t] = g4[t];
      if (tid < 100) sm->b1[tid] = b1_g[i * 100 + tid];
      const float* g = W2_g + i * 75000;
      for (int t = tid; t < 15000; t += NTHREADS) {
        int h = t / 150;
        int c = t - h * 150;
        int u = c / 3;
        int p = c - u * 3;
        sm->W2[h][c] = __float2half_rn(g[h * 750 + u * 15 + p]);
      }
    }
    __syncthreads();

    // ---- stage 1a: radial MLP hidden -> overlay slots 9/10 ----
    #pragma unroll
    for (int j = 0; j < 4; j++) {
      int h = ln + 32 * j;
      if (h < HIDC) {
        float a0 = 0.0f, a1 = 0.0f;
        #pragma unroll
        for (int b = 0; b < NBC; b++) {
          float w1 = sm->W1[b][h];
          a0 = fmaf(sm->emb[e0][b], w1, a0);
          a1 = fmaf(sm->emb[e1][b], w1, a1);
        }
        HID(e0, h) = geluf(a0 * 0.31622776601683794f + sm->b1[h]);
        HID(e1, h) = geluf(a1 * 0.31622776601683794f + sm->b1[h]);
      }
    }
    __syncwarp();

    // ---- stage 1b: wv (packed) ----
    // WV0[0]=(wv000,wv001) WV0[1]=(wv002,wv010) WV0[2]=(wv011,wv012); WV1 same for e1
    u64 WV0[3] = {0ull, 0ull, 0ull};
    u64 WV1[3] = {0ull, 0ull, 0ull};
    if (act) {
      #pragma unroll 4
      for (int h = 0; h < HIDC; h++) {
        float h0v = HID(e0, h);
        float h1v = HID(e1, h);
        const __half* w2p = &sm->W2[h][6 * ln];
        float2 c0 = ldh2(w2p), c1 = ldh2(w2p + 2), c2 = ldh2(w2p + 4);
        u64 C0 = pk(c0.x, c0.y), C1 = pk(c1.x, c1.y), C2 = pk(c2.x, c2.y);
        u64 H0 = pk(h0v, h0v), H1 = pk(h1v, h1v);
        fma2(WV0[0], H0, C0); fma2(WV0[1], H0, C1); fma2(WV0[2], H0, C2);
        fma2(WV1[0], H1, C0); fma2(WV1[1], H1, C1); fma2(WV1[2], H1, C2);
      }
    }
    float wv[2][2][3];
    upk(wv[0][0][0], wv[0][0][1], WV0[0]);
    upk(wv[0][0][2], wv[0][1][0], WV0[1]);
    upk(wv[0][1][1], wv[0][1][2], WV0[2]);
    upk(wv[1][0][0], wv[1][0][1], WV1[0]);
    upk(wv[1][0][2], wv[1][1][0], WV1[1]);
    upk(wv[1][1][1], wv[1][1][2], WV1[2]);

    // ---- stage 2: source matvecs (packed over ch) ----
    u64 H0p = 0ull, H1p = 0ull, SC0p = 0ull, SC1p = 0ull;
    if (act) {
      #pragma unroll 5
      for (int t = 0; t < MULC; t++) {
        float s0 = sm->s[e0][t];
        float s1 = sm->s[e1][t];
        float2 wl = ldh2(&sm->Wl1[t][u0]);
        float2 ws = ldh2(&sm->Wsc[0][t][u0]);
        u64 WL = pk(wl.x, wl.y), WS = pk(ws.x, ws.y);
        u64 S0 = pk(s0, s0), S1 = pk(s1, s1);
        fma2(H0p, S0, WL);
        fma2(SC0p, S0, WS);
        fma2(H1p, S1, WL);
        fma2(SC1p, S1, WS);
      }
    }
    float h0a[2][2], sca[2][2];
    upk(h0a[0][0], h0a[0][1], H0p);
    upk(h0a[1][0], h0a[1][1], H1p);
    upk(sca[0][0], sca[0][1], SC0p);
    upk(sca[1][0], sca[1][1], SC1p);
    __syncwarp();
    if (act) {
      #pragma unroll
      for (int e = 0; e < 2; e++) {
        int le = e0 + e;
        #pragma unroll
        for (int ch = 0; ch < 2; ch++) {
          int u = u0 + ch;
          float h0 = h0a[e][ch] * INVS50;
          float* xr = sm->X[le][u];
          xr[9]  = h0 * wv[e][ch][0] * 0.1f;
          xr[10] = h0 * wv[e][ch][1] * 0.1f;
          xr[11] = h0 * wv[e][ch][2] * 0.1f;
          sm->s[le][u] = siluf(CS * sca[e][ch] * INVS50);
        }
      }
    }
    __syncwarp();

    // ---- stage 3: packed f32x2; row pairs (x1,x2)(x3,x0)(x4,x5)(x6,x7)(x8,a0)(a1,a2) ----
    u64 A[2][2][6] = {};
    if (act) {
      #pragma unroll 2
      for (int u = 0; u < MULC; u++) {
        const ulonglong2* x0p = reinterpret_cast<const ulonglong2*>(sm->X[e0][u]);
        ulonglong2 xa0 = x0p[0], xb0 = x0p[1], xc0 = x0p[2];
        const ulonglong2* x1p = reinterpret_cast<const ulonglong2*>(sm->X[e1][u]);
        ulonglong2 xa1 = x1p[0], xb1 = x1p[1], xc1 = x1p[2];
        float2 ws0 = ldh2(&sm->Wsc[0][u][u0]);
        float2 ws1 = ldh2(&sm->Wsc[1][u][u0]);
        float2 ws2 = ldh2(&sm->Wsc[2][u][u0]);
        float2 l0 = ldh2(&sm->Wl2[0][u][u0]);
        float2 l1 = ldh2(&sm->Wl2[1][u][u0]);
        float2 l2 = ldh2(&sm->Wl2[2][u][u0]);
        u64 Q0x = pk(ws1.x, ws1.x);
        u64 Q1x = pk(ws1.x, ws0.x);
        u64 Q2x = pk(ws2.x, ws2.x);
        u64 Q3x = pk(ws2.x, l0.x);
        u64 Q4x = pk(l1.x, l2.x);
        u64 Q0y = pk(ws1.y, ws1.y);
        u64 Q1y = pk(ws1.y, ws0.y);
        u64 Q2y = pk(ws2.y, ws2.y);
        u64 Q3y = pk(ws2.y, l0.y);
        u64 Q4y = pk(l1.y, l2.y);
        fma2(A[0][0][0], xa0.x, Q0x);
        fma2(A[0][0][1], xa0.y, Q1x);
        fma2(A[0][0][2], xb0.x, Q2x);
        fma2(A[0][0][3], xb0.y, Q2x);
        fma2(A[0][0][4], xc0.x, Q3x);
        fma2(A[0][0][5], xc0.y, Q4x);
        fma2(A[0][1][0], xa0.x, Q0y);
        fma2(A[0][1][1], xa0.y, Q1y);
        fma2(A[0][1][2], xb0.x, Q2y);
        fma2(A[0][1][3], xb0.y, Q2y);
        fma2(A[0][1][4], xc0.x, Q3y);
        fma2(A[0][1][5], xc0.y, Q4y);
        fma2(A[1][0][0], xa1.x, Q0x);
        fma2(A[1][0][1], xa1.y, Q1x);
        fma2(A[1][0][2], xb1.x, Q2x);
        fma2(A[1][0][3], xb1.y, Q2x);
        fma2(A[1][0][4], xc1.x, Q3x);
        fma2(A[1][0][5], xc1.y, Q4x);
        fma2(A[1][1][0], xa1.x, Q0y);
        fma2(A[1][1][1], xa1.y, Q1y);
        fma2(A[1][1][2], xb1.x, Q2y);
        fma2(A[1][1][3], xb1.y, Q2y);
        fma2(A[1][1][4], xc1.x, Q3y);
        fma2(A[1][1][5], xc1.y, Q4y);
      }
    }
    __syncwarp();   // all lanes done reading X
    if (act) {
      #pragma unroll
      for (int e = 0; e < 2; e++) {
        int le = e0 + e;
        const float* shl = sm->shv[le];
        #pragma unroll
        for (int ch = 0; ch < 2; ch++) {
          int u = u0 + ch;
          float ac0, ac1, ac2, ac3, ac4, ac5, ac6, ac7, ac8, b0, b1v, b2;
          upk(ac1, ac2, A[e][ch][0]);
          upk(ac3, ac0, A[e][ch][1]);
          upk(ac4, ac5, A[e][ch][2]);
          upk(ac6, ac7, A[e][ch][3]);
          upk(ac8, b0,  A[e][ch][4]);
          upk(b1v, b2,  A[e][ch][5]);
          float* xr = sm->X[le][u];
          xr[3] = CS * INVS50 * ac0 + CXK0 * b0;
          xr[0] = CS * INVS50 * ac1 + CXK1 * b1v * shl[1];
          xr[1] = CS * INVS50 * ac2 + CXK1 * b1v * shl[2];
          xr[2] = CS * INVS50 * ac3 + CXK1 * b1v * shl[3];
          xr[4] = CS * INVS50 * ac4 + CXK2 * b2 * shl[4];
          xr[5] = CS * INVS50 * ac5 + CXK2 * b2 * shl[5];
          xr[6] = CS * INVS50 * ac6 + CXK2 * b2 * shl[6];
          xr[7] = CS * INVS50 * ac7 + CXK2 * b2 * shl[7];
          xr[8] = CS * INVS50 * ac8 + CXK2 * b2 * shl[8];
        }
      }
    }
    __syncwarp();

    // ---- stage 4: gate (packed over ch) ----
    u64 GA0 = 0ull, GA1 = 0ull;
    if (act) {
      #pragma unroll 5
      for (int u = 0; u < MULC; u++) {
        float t0 = sm->X[e0][u][3];   // x0 at phys 3
        float t1 = sm->X[e1][u][3];
        float2 wg = ldh2(&sm->Wg[u][u0]);
        u64 WG = pk(wg.x, wg.y);
        u64 T0 = pk(t0, t0), T1 = pk(t1, t1);
        fma2(GA0, T0, WG);
        fma2(GA1, T1, WG);
      }
    }
    float ga[2][2];
    upk(ga[0][0], ga[0][1], GA0);
    upk(ga[1][0], ga[1][1], GA1);
    __syncwarp();
    if (act) {
      #pragma unroll
      for (int e = 0; e < 2; e++) {
        int le = e0 + e;
        #pragma unroll
        for (int ch = 0; ch < 2; ch++) {
          int u = u0 + ch;
          float g = sigmoidf(ga[e][ch] * INVS50);
          float* xr = sm->X[le][u];
          float4 Af = *reinterpret_cast<const float4*>(xr);
          float4 Bf = *reinterpret_cast<const float4*>(xr + 4);
          float x8 = xr[8];
          float4 qa = make_float4(Af.x * g, Af.y * g, Af.z * g, siluf(Af.w));
          float4 qb = make_float4(Bf.x * g, Bf.y * g, Bf.z * g, Bf.w * g);
          *reinterpret_cast<float4*>(xr)     = qa;
          *reinterpret_cast<float4*>(xr + 4) = qb;
          xr[8] = x8 * g;
        }
      }
    }
    __syncwarp();
  }

  // ---------------- output: x1..x3 at phys 0..2 ----------------
  {
    float p[2][3] = {};
    if (act) {
      float wo0 = Wout_g[u0];
      float wo1 = Wout_g[u0 + 1];
      #pragma unroll
      for (int e = 0; e < 2; e++) {
        int le = e0 + e;
        const float* r0 = sm->X[le][u0];
        const float* r1 = sm->X[le][u0 + 1];
        p[e][0] = r0[0] * wo0 + r1[0] * wo1;
        p[e][1] = r0[1] * wo0 + r1[1] * wo1;
        p[e][2] = r0[2] * wo0 + r1[2] * wo1;
      }
    }
    #pragma unroll
    for (int off = 16; off; off >>= 1) {
      #pragma unroll
      for (int e = 0; e < 2; e++) {
        p[e][0] += __shfl_xor_sync(0xffffffffu, p[e][0], off);
        p[e][1] += __shfl_xor_sync(0xffffffffu, p[e][1], off);
        p[e][2] += __shfl_xor_sync(0xffffffffu, p[e][2], off);
      }
    }
    if (ln == 0) {
      int eg0 = blockIdx.x * TE + e0;
      float* od = out + (size_t)(2 * eg0) * 3;
      od[0] = 0.0f; od[1] = 0.0f; od[2] = 0.0f;
      od[3] = p[0][0] * INVS50;
      od[4] = p[0][1] * INVS50;
      od[5] = p[0][2] * INVS50;
      od[6] = 0.0f; od[7] = 0.0f; od[8] = 0.0f;
      od[9]  = p[1][0] * INVS50;
      od[10] = p[1][1] * INVS50;
      od[11] = p[1][2] * INVS50;
    }
  }
}

extern "C" void kernel_launch(void* const* d_in, const int* in_sizes, int n_in,
                              void* d_out, int out_size) {
  const float* node_pos = (const float*)d_in[0];
  const float* bar_alpha = (const float*)d_in[1];
  const float* W_embed  = (const float*)d_in[2];
  const float* Wsc      = (const float*)d_in[3];
  const float* Wlin1    = (const float*)d_in[4];
  const float* W1       = (const float*)d_in[5];
  const float* b1       = (const float*)d_in[6];
  const float* W2       = (const float*)d_in[7];
  const float* Wlin2    = (const float*)d_in[8];
  const float* Wgate    = (const float*)d_in[9];
  const float* W_out    = (const float*)d_in[10];
  float* out = (float*)d_out;

  int E = in_sizes[0] / 6;
  size_t smem = sizeof(SM);
  cudaFuncSetAttribute(slinky_kernel, cudaFuncAttributeMaxDynamicSharedMemorySize, (int)smem);
  slinky_kernel<<<E / TE, NTHREADS, smem>>>(node_pos, bar_alpha, W_embed, Wsc, Wlin1,
                                            W1, b1, W2, Wlin2, Wgate, W_out, out);
}